// round 10
// baseline (speedup 1.0000x reference)
#include <cuda_runtime.h>
#include <cstdint>

#define NN 100000
#define EE 1600000
#define DD 128
#define NG 64

// ---------------- scratch (static device globals; no allocation) ----------------
__device__ int      g_ei64, g_b64;
__device__ int      g_degi[NN];
__device__ int      g_start[NN];
__device__ int      g_cursor[NN];
__device__ int      g_bsum[512];
__device__ int      g_cnti[NG];
__device__ int      g_csr[EE];
__device__ float    g_winv[NN];
__device__ float    g_cinv[NG];
__device__ unsigned g_pb[(size_t)NN * 64];    // layer-1 P packed bf16x2
__device__ unsigned g_qb[(size_t)NN * 64];    // layer-1 Q packed bf16x2
__device__ unsigned g_pb2[(size_t)NN * 64];   // layer-2 P
__device__ unsigned g_qb2[(size_t)NN * 64];   // layer-2 Q
__device__ float    g_z[(size_t)NN * 4];
__device__ unsigned g_wspT[4][2][DD][64];     // pre-split W, transposed [mat][plane][n][k2]
__device__ float    g_Wcl[DD * 2];
__device__ float    g_Wcr[DD * 2];
__device__ float    g_cb[2];
__device__ float    g_acc[NG * 2];

// ---------------- helpers ----------------
__device__ __forceinline__ unsigned pack_bf2(float lo, float hi) {
    unsigned r;
    asm("cvt.rn.bf16x2.f32 %0, %1, %2;" : "=r"(r) : "f"(hi), "f"(lo));
    return r;
}
__device__ __forceinline__ void split2(float x0, float x1, unsigned& p0, unsigned& p1) {
    p0 = pack_bf2(x0, x1);
    float h0 = __uint_as_float(p0 << 16);
    float h1 = __uint_as_float(p0 & 0xFFFF0000u);
    p1 = pack_bf2(x0 - h0, x1 - h1);
}
__device__ __forceinline__ void mma_bf16(float* d, const unsigned* a, const unsigned* b) {
    asm volatile(
        "mma.sync.aligned.m16n8k16.row.col.f32.bf16.bf16.f32 "
        "{%0,%1,%2,%3}, {%4,%5,%6,%7}, {%8,%9}, {%0,%1,%2,%3};"
        : "+f"(d[0]), "+f"(d[1]), "+f"(d[2]), "+f"(d[3])
        : "r"(a[0]), "r"(a[1]), "r"(a[2]), "r"(a[3]), "r"(b[0]), "r"(b[1]));
}
__device__ __forceinline__ void ldsm_x4(unsigned& r0, unsigned& r1, unsigned& r2, unsigned& r3,
                                        unsigned saddr) {
    asm volatile("ldmatrix.sync.aligned.m8n8.x4.shared.b16 {%0,%1,%2,%3}, [%4];"
                 : "=r"(r0), "=r"(r1), "=r"(r2), "=r"(r3) : "r"(saddr));
}
__device__ __forceinline__ void acc_bf2(float4& acc, uint2 v) {
    acc.x += __uint_as_float(v.x << 16);
    acc.y += __uint_as_float(v.x & 0xFFFF0000u);
    acc.z += __uint_as_float(v.y << 16);
    acc.w += __uint_as_float(v.y & 0xFFFF0000u);
}

__device__ __forceinline__ int ld_ei(const void* p, long long i) {
    return g_ei64 ? (int)((const long long*)p)[i] : ((const int*)p)[i];
}
__device__ __forceinline__ int ld_b(const void* p, long long i) {
    return g_b64 ? (int)((const long long*)p)[i] : ((const int*)p)[i];
}

// ---------------- K0: zero + presplit + detect (role-split, all independent) ----------------
__global__ void __launch_bounds__(256) init_kernel(const void* ei, const void* batch,
                                                   const float* __restrict__ Wl1,
                                                   const float* __restrict__ Wr1,
                                                   const float* __restrict__ Wl2,
                                                   const float* __restrict__ Wr2) {
    int bid = blockIdx.x;
    if (bid < 391) {                       // zero role
        int i = bid * 256 + threadIdx.x;
        if (i < NN) g_degi[i] = 0;
        if (i < NG) g_cnti[i] = 0;
        if (i < NG * 2) g_acc[i] = 0.0f;
    } else if (bid < 519) {                // presplit role
        int idx = (bid - 391) * 256 + threadIdx.x;   // 0..32767
        int mat = idx >> 13;
        int rem = idx & 8191;
        int k2 = rem >> 7;
        int n = rem & 127;
        const float* W = (mat == 0) ? Wl1 : (mat == 1) ? Wr1 : (mat == 2) ? Wl2 : Wr2;
        float w0 = W[(2 * k2) * DD + n];
        float w1 = W[(2 * k2 + 1) * DD + n];
        unsigned p0, p1;
        split2(w0, w1, p0, p1);
        g_wspT[mat][0][n][k2] = p0;
        g_wspT[mat][1][n][k2] = p1;
    } else if (threadIdx.x == 0) {         // detect role
        const long long* p = (const long long*)ei;
        bool e64 = true;
        #pragma unroll
        for (int i = 0; i < 16; i++) {
            long long v = p[(size_t)i * 99991];
            if (v < 0 || v >= NN) e64 = false;
        }
        g_ei64 = e64 ? 1 : 0;
        const long long* q = (const long long*)batch;
        bool b64 = true;
        #pragma unroll
        for (int i = 0; i < 8; i++) {
            long long v = q[NN / 2 - 1 - i * 37];
            if (v < 0 || v >= NG) b64 = false;
        }
        g_b64 = b64 ? 1 : 0;
    }
}

// ---------------- fused degree + batch histogram ----------------
__global__ void __launch_bounds__(256) deg_cnt_kernel(const void* __restrict__ ei,
                                                      const void* __restrict__ batch) {
    __shared__ int sh[NG];
    if (threadIdx.x < NG) sh[threadIdx.x] = 0;
    __syncthreads();
    int e = blockIdx.x * 256 + threadIdx.x;
    if (e < EE) {
        unsigned d = (unsigned)ld_ei(ei, (long long)EE + e);
        if (d < NN) atomicAdd(&g_degi[d], 1);
    }
    if (e < NN) {
        unsigned g = (unsigned)ld_b(batch, e);
        if (g < NG) atomicAdd(&sh[g], 1);
    }
    __syncthreads();
    if (threadIdx.x < NG && sh[threadIdx.x] != 0) atomicAdd(&g_cnti[threadIdx.x], sh[threadIdx.x]);
}

// ---------------- scans / CSR placement ----------------
__global__ void __launch_bounds__(256) scan1_kernel() {
    __shared__ int sdata[256];
    int t = threadIdx.x;
    int i = blockIdx.x * 256 + t;
    int v = (i < NN) ? g_degi[i] : 0;
    sdata[t] = v;
    __syncthreads();
    #pragma unroll
    for (int off = 1; off < 256; off <<= 1) {
        int x = (t >= off) ? sdata[t - off] : 0;
        __syncthreads();
        sdata[t] += x;
        __syncthreads();
    }
    int incl = sdata[t];
    if (i < NN) g_start[i] = incl - v;
    if (t == 255) g_bsum[blockIdx.x] = incl;
}

__global__ void __launch_bounds__(512) scan2_kernel(int nb) {
    __shared__ int sdata[512];
    int t = threadIdx.x;
    int v = (t < nb) ? g_bsum[t] : 0;
    sdata[t] = v;
    __syncthreads();
    #pragma unroll
    for (int off = 1; off < 512; off <<= 1) {
        int x = (t >= off) ? sdata[t - off] : 0;
        __syncthreads();
        sdata[t] += x;
        __syncthreads();
    }
    if (t < nb) g_bsum[t] = sdata[t] - v;
    if (t < NG) g_cinv[t] = 1.0f / fmaxf((float)g_cnti[t], 1.0f);
}

__global__ void __launch_bounds__(256) scan3_kernel() {
    int i = blockIdx.x * 256 + threadIdx.x;
    if (i >= NN) return;
    int s = g_start[i] + g_bsum[i >> 8];
    g_start[i] = s;
    g_cursor[i] = s;
    g_winv[i] = 1.0f / fmaxf((float)g_degi[i], 1.0f);
}

__global__ void __launch_bounds__(256) place_kernel(const void* __restrict__ ei) {
    int e = blockIdx.x * blockDim.x + threadIdx.x;
    if (e >= EE) return;
    unsigned s = (unsigned)ld_ei(ei, e);
    unsigned d = (unsigned)ld_ei(ei, (long long)EE + e);
    if (s >= NN || d >= NN) return;
    int pos = atomicAdd(&g_cursor[d], 1);
    g_csr[pos] = (int)s;
}

// ---------------- bf16x3 GEMM: cp.async double-buffered B; optional fused gather A ----------------
extern __shared__ unsigned sm_dyn[];
#define AS_STR 68
#define BS_STR 12
#define GEMM_SMEM ((2 * 128 * AS_STR + 4 * 128 * BS_STR) * 4)

__device__ __forceinline__ void issue_b(const unsigned* __restrict__ WT, int ko2,
                                        unsigned sa0, unsigned sa1, int tid) {
    #pragma unroll
    for (int i = 0; i < 4; i++) {
        int slot = tid + 128 * i;
        int pl = slot >> 8;
        int rem = slot & 255;
        int n = rem >> 1;
        int half = rem & 1;
        const unsigned* src = WT + ((size_t)pl * 128 + n) * 64 + ko2 + half * 4;
        unsigned dst = (pl ? sa1 : sa0) + (unsigned)(n * BS_STR + half * 4) * 4;
        asm volatile("cp.async.cg.shared.global [%0], [%1], 16;" :: "r"(dst), "l"(src));
    }
}

template <int GATHER>
__global__ void __launch_bounds__(128) gemm_bf16x3_kernel(
        const float* __restrict__ X,
        int matL, int matR,
        const unsigned* __restrict__ Pin, const unsigned* __restrict__ Qin,
        const float* __restrict__ bias,
        unsigned* __restrict__ Pout, unsigned* __restrict__ Qout) {
    unsigned* As0 = sm_dyn;                       // [128][AS_STR]
    unsigned* As1 = sm_dyn + 128 * AS_STR;
    unsigned* Bb = sm_dyn + 2 * 128 * AS_STR;     // 4 plane-buffers of 128*BS_STR

    int tid = threadIdx.x;
    int warp = tid >> 5, lane = tid & 31;
    int g = lane >> 2, t = lane & 3;
    int wm = (warp >> 1) * 64, wn = (warp & 1) * 64;
    int row0 = blockIdx.x * 128;

    unsigned bsa[2][2];
    #pragma unroll
    for (int bf = 0; bf < 2; bf++)
        #pragma unroll
        for (int pl = 0; pl < 2; pl++)
            bsa[bf][pl] = (unsigned)__cvta_generic_to_shared(Bb + (bf * 2 + pl) * 128 * BS_STR);

    const unsigned* WTs[2] = {&g_wspT[matL][0][0][0], &g_wspT[matR][0][0][0]};

    // preload B chunk 0 into buffer 0 (overlaps the A phase)
    issue_b(WTs[0], 0, bsa[0][0], bsa[0][1], tid);
    asm volatile("cp.async.commit_group;");

    // ---- A phase: build split A tile in smem ----
    if (GATHER == 0) {
        #pragma unroll
        for (int i = 0; i < 32; i++) {
            int slot = tid + 128 * i;
            int m = slot >> 5;
            int k4 = (slot & 31) * 4;
            int r = row0 + m;
            float4 av = (r < NN) ? *(const float4*)(X + (size_t)r * DD + k4)
                                 : make_float4(0.f, 0.f, 0.f, 0.f);
            unsigned p0, p1, q0, q1;
            split2(av.x, av.y, p0, p1);
            split2(av.z, av.w, q0, q1);
            int k2 = k4 >> 1;
            *(uint2*)&As0[m * AS_STR + k2] = make_uint2(p0, q0);
            *(uint2*)&As1[m * AS_STR + k2] = make_uint2(p1, q1);
        }
    } else {
        // fused SAGE gather: h = relu(winv * sum P[nbr] + Q + bias), split to smem
        float4 b4 = ((const float4*)bias)[lane];
        for (int rr = 0; rr < 32; rr++) {
            int m = warp * 32 + rr;
            int r = row0 + m;
            float4 h = make_float4(0.f, 0.f, 0.f, 0.f);
            if (r < NN) {
                int s = g_start[r], dg = g_degi[r];
                float4 acc = make_float4(0.f, 0.f, 0.f, 0.f);
                int j = 0;
                for (; j + 2 <= dg; j += 2) {
                    int s0 = g_csr[s + j], s1 = g_csr[s + j + 1];
                    uint2 v0 = ((const uint2*)(Pin + (size_t)s0 * 64))[lane];
                    uint2 v1 = ((const uint2*)(Pin + (size_t)s1 * 64))[lane];
                    acc_bf2(acc, v0);
                    acc_bf2(acc, v1);
                }
                if (j < dg) {
                    uint2 v = ((const uint2*)(Pin + (size_t)g_csr[s + j] * 64))[lane];
                    acc_bf2(acc, v);
                }
                float w = g_winv[r];
                float4 q4 = make_float4(0.f, 0.f, 0.f, 0.f);
                acc_bf2(q4, ((const uint2*)(Qin + (size_t)r * 64))[lane]);
                h.x = fmaxf(acc.x * w + q4.x + b4.x, 0.f);
                h.y = fmaxf(acc.y * w + q4.y + b4.y, 0.f);
                h.z = fmaxf(acc.z * w + q4.z + b4.z, 0.f);
                h.w = fmaxf(acc.w * w + q4.w + b4.w, 0.f);
            }
            unsigned p0, p1, q0, q1;
            split2(h.x, h.y, p0, p1);
            split2(h.z, h.w, q0, q1);
            *(uint2*)&As0[m * AS_STR + 2 * lane] = make_uint2(p0, q0);
            *(uint2*)&As1[m * AS_STR + 2 * lane] = make_uint2(p1, q1);
        }
    }

    asm volatile("cp.async.wait_group 0;" ::: "memory");
    __syncthreads();

    // LDSM lane-address components (validated mapping)
    int arow = (lane & 7) + ((lane & 8) ? 8 : 0);
    int akb = (lane & 16) ? 16 : 0;
    int brow = (lane & 7) + ((lane & 16) ? 8 : 0);
    int bkb = (lane & 8) ? 16 : 0;

    unsigned a0base = (unsigned)__cvta_generic_to_shared(As0) + (wm + arow) * (AS_STR * 4) + akb;
    unsigned a1base = (unsigned)__cvta_generic_to_shared(As1) + (wm + arow) * (AS_STR * 4) + akb;
    unsigned bbase[2][2];
    #pragma unroll
    for (int bf = 0; bf < 2; bf++)
        #pragma unroll
        for (int pl = 0; pl < 2; pl++)
            bbase[bf][pl] = bsa[bf][pl] + (wn + brow) * (BS_STR * 4) + bkb;

    float acc[4][8][4];
    #pragma unroll
    for (int a = 0; a < 4; a++)
        #pragma unroll
        for (int b = 0; b < 8; b++)
            #pragma unroll
            for (int c = 0; c < 4; c++) acc[a][b][c] = 0.0f;

    // ---- 16-chunk pipeline: 0..7 phase 0 (matL), 8..15 phase 1 (matR) ----
    #pragma unroll
    for (int c = 0; c < 16; c++) {
        const int cur = c & 1;
        if (c < 15) {
            issue_b(WTs[(c + 1) >> 3], ((c + 1) & 7) * 8, bsa[cur ^ 1][0], bsa[cur ^ 1][1], tid);
            asm volatile("cp.async.commit_group;");
        }
        int ko2 = (c & 7) * 8;
        unsigned a0f[4][4], a1f[4][4];
        #pragma unroll
        for (int mt = 0; mt < 4; mt++) {
            unsigned off = mt * 16 * (AS_STR * 4) + ko2 * 4;
            ldsm_x4(a0f[mt][0], a0f[mt][1], a0f[mt][2], a0f[mt][3], a0base + off);
            ldsm_x4(a1f[mt][0], a1f[mt][1], a1f[mt][2], a1f[mt][3], a1base + off);
        }
        #pragma unroll
        for (int ntp = 0; ntp < 4; ntp++) {
            unsigned off = ntp * 16 * (BS_STR * 4);
            unsigned p0r0, p0r1, p0r2, p0r3, p1r0, p1r1, p1r2, p1r3;
            ldsm_x4(p0r0, p0r1, p0r2, p0r3, bbase[cur][0] + off);
            ldsm_x4(p1r0, p1r1, p1r2, p1r3, bbase[cur][1] + off);
            unsigned bh0[2] = {p0r0, p0r1}, bh1[2] = {p0r2, p0r3};
            unsigned bl0[2] = {p1r0, p1r1}, bl1[2] = {p1r2, p1r3};
            #pragma unroll
            for (int mt = 0; mt < 4; mt++) {
                mma_bf16(acc[mt][2 * ntp], a0f[mt], bh0);
                mma_bf16(acc[mt][2 * ntp], a0f[mt], bl0);
                mma_bf16(acc[mt][2 * ntp], a1f[mt], bh0);
                mma_bf16(acc[mt][2 * ntp + 1], a0f[mt], bh1);
                mma_bf16(acc[mt][2 * ntp + 1], a0f[mt], bl1);
                mma_bf16(acc[mt][2 * ntp + 1], a1f[mt], bh1);
            }
        }
        if (c == 7) {   // end of phase 0: write P, reset accumulators
            #pragma unroll
            for (int mt = 0; mt < 4; mt++) {
                #pragma unroll
                for (int nt = 0; nt < 8; nt++) {
                    int r = row0 + wm + mt * 16 + g;
                    int cc = wn + nt * 8 + 2 * t;
                    if (r < NN)
                        Pout[(size_t)r * 64 + (cc >> 1)] = pack_bf2(acc[mt][nt][0], acc[mt][nt][1]);
                    if (r + 8 < NN)
                        Pout[(size_t)(r + 8) * 64 + (cc >> 1)] = pack_bf2(acc[mt][nt][2], acc[mt][nt][3]);
                    acc[mt][nt][0] = acc[mt][nt][1] = acc[mt][nt][2] = acc[mt][nt][3] = 0.0f;
                }
            }
        }
        if (c < 15) {
            asm volatile("cp.async.wait_group 0;" ::: "memory");
            __syncthreads();
        }
    }

    // ---- phase-1 epilogue: write Q ----
    #pragma unroll
    for (int mt = 0; mt < 4; mt++) {
        #pragma unroll
        for (int nt = 0; nt < 8; nt++) {
            int r = row0 + wm + mt * 16 + g;
            int cc = wn + nt * 8 + 2 * t;
            if (r < NN)
                Qout[(size_t)r * 64 + (cc >> 1)] = pack_bf2(acc[mt][nt][0], acc[mt][nt][1]);
            if (r + 8 < NN)
                Qout[(size_t)(r + 8) * 64 + (cc >> 1)] = pack_bf2(acc[mt][nt][2], acc[mt][nt][3]);
        }
    }
}

// ---------------- layer-3 fold ----------------
__global__ void foldW_kernel(const float* __restrict__ Wl3, const float* __restrict__ Wr3,
                             const float* __restrict__ bl3, const float* __restrict__ Wlin,
                             const float* __restrict__ blin) {
    int k = threadIdx.x;
    float a0 = 0.f, a1 = 0.f, b0 = 0.f, b1 = 0.f;
    for (int m = 0; m < DD; m++) {
        float wl = Wl3[k * DD + m], wr = Wr3[k * DD + m];
        float l0 = Wlin[m * 2 + 0], l1 = Wlin[m * 2 + 1];
        a0 += wl * l0; a1 += wl * l1;
        b0 += wr * l0; b1 += wr * l1;
    }
    g_Wcl[k * 2 + 0] = a0; g_Wcl[k * 2 + 1] = a1;
    g_Wcr[k * 2 + 0] = b0; g_Wcr[k * 2 + 1] = b1;
    if (k < 2) {
        float cv = blin[k];
        for (int m = 0; m < DD; m++) cv += bl3[m] * Wlin[m * 2 + k];
        g_cb[k] = cv;
    }
}

// ---------------- layer-2 gather fused with layer-3 projection -> z ----------------
__global__ void __launch_bounds__(256) gather2z_kernel(const unsigned* __restrict__ P,
                                                       const unsigned* __restrict__ Q,
                                                       const float* __restrict__ bias) {
    int node = blockIdx.x * 8 + (threadIdx.x >> 5);
    int lane = threadIdx.x & 31;
    int s = g_start[node];
    int d = g_degi[node];
    float4 acc = make_float4(0.f, 0.f, 0.f, 0.f);
    for (int j = 0; j < d; j++) {
        int src = g_csr[s + j];
        uint2 v = ((const uint2*)(P + (size_t)src * 64))[lane];
        acc_bf2(acc, v);
    }
    float w = g_winv[node];
    float4 q = make_float4(0.f, 0.f, 0.f, 0.f);
    acc_bf2(q, ((const uint2*)(Q + (size_t)node * 64))[lane]);
    float4 b = ((const float4*)bias)[lane];
    float hv[4];
    hv[0] = fmaxf(acc.x * w + q.x + b.x, 0.0f);
    hv[1] = fmaxf(acc.y * w + q.y + b.y, 0.0f);
    hv[2] = fmaxf(acc.z * w + q.z + b.z, 0.0f);
    hv[3] = fmaxf(acc.w * w + q.w + b.w, 0.0f);
    float s0 = 0.f, s1 = 0.f, s2 = 0.f, s3 = 0.f;
    #pragma unroll
    for (int j = 0; j < 4; j++) {
        int k = lane * 4 + j;
        s0 += hv[j] * g_Wcl[k * 2 + 0];
        s1 += hv[j] * g_Wcl[k * 2 + 1];
        s2 += hv[j] * g_Wcr[k * 2 + 0];
        s3 += hv[j] * g_Wcr[k * 2 + 1];
    }
    #pragma unroll
    for (int o = 16; o > 0; o >>= 1) {
        s0 += __shfl_down_sync(0xFFFFFFFFu, s0, o);
        s1 += __shfl_down_sync(0xFFFFFFFFu, s1, o);
        s2 += __shfl_down_sync(0xFFFFFFFFu, s2, o);
        s3 += __shfl_down_sync(0xFFFFFFFFu, s3, o);
    }
    if (lane == 0) ((float4*)g_z)[node] = make_float4(s0, s1, s2, s3);
}

// ---------------- layer-3 pooled reduction ----------------
__global__ void __launch_bounds__(256) pool3_kernel(const void* __restrict__ batch) {
    __shared__ float sh[NG * 2];
    for (int i = threadIdx.x; i < NG * 2; i += blockDim.x) sh[i] = 0.0f;
    __syncthreads();
    int n = blockIdx.x * 256 + threadIdx.x;
    if (n < NN) {
        int s = g_start[n], d = g_degi[n];
        float s0 = 0.f, s1 = 0.f;
        for (int j = 0; j < d; j++) {
            int src = g_csr[s + j];
            float2 zl = *(const float2*)(g_z + (size_t)src * 4);
            s0 += zl.x; s1 += zl.y;
        }
        float w = g_winv[n];
        unsigned gg = (unsigned)ld_b(batch, n);
        if (gg < NG) {
            float ci = g_cinv[gg];
            float2 zr = *(const float2*)(g_z + (size_t)n * 4 + 2);
            atomicAdd(&sh[gg * 2 + 0], ci * (w * s0 + zr.x));
            atomicAdd(&sh[gg * 2 + 1], ci * (w * s1 + zr.y));
        }
    }
    __syncthreads();
    for (int i = threadIdx.x; i < NG * 2; i += blockDim.x)
        if (sh[i] != 0.0f) atomicAdd(&g_acc[i], sh[i]);
}

__global__ void finalize_kernel(float* __restrict__ out) {
    int t = threadIdx.x;
    if (t < NG * 2) out[t] = g_acc[t] + g_cb[t & 1];
}

// ---------------- host launcher ----------------
extern "C" void kernel_launch(void* const* d_in, const int* in_sizes, int n_in,
                              void* d_out, int out_size) {
    const float* x = (const float*)d_in[0];
    const void* ei = d_in[1];
    const void* batch = d_in[2];
    const float* Wl1 = (const float*)d_in[3];
    const float* bl1 = (const float*)d_in[4];
    const float* Wr1 = (const float*)d_in[5];
    const float* Wl2 = (const float*)d_in[6];
    const float* bl2 = (const float*)d_in[7];
    const float* Wr2 = (const float*)d_in[8];
    const float* Wl3 = (const float*)d_in[9];
    const float* bl3 = (const float*)d_in[10];
    const float* Wr3 = (const float*)d_in[11];
    const float* Wlin = (const float*)d_in[12];
    const float* blin = (const float*)d_in[13];
    float* out = (float*)d_out;

    // __device__ symbols are not host pointers: resolve real addresses.
    unsigned *pp = nullptr, *qp = nullptr, *pp2 = nullptr, *qp2 = nullptr;
    cudaGetSymbolAddress((void**)&pp, g_pb);
    cudaGetSymbolAddress((void**)&qp, g_qb);
    cudaGetSymbolAddress((void**)&pp2, g_pb2);
    cudaGetSymbolAddress((void**)&qp2, g_qb2);

    cudaFuncSetAttribute(gemm_bf16x3_kernel<0>,
                         cudaFuncAttributeMaxDynamicSharedMemorySize, GEMM_SMEM);
    cudaFuncSetAttribute(gemm_bf16x3_kernel<1>,
                         cudaFuncAttributeMaxDynamicSharedMemorySize, GEMM_SMEM);

    const int nb = (NN + 255) / 256;           // 391
    const int gemm_blocks = (NN + 127) / 128;  // 782

    init_kernel<<<520, 256>>>(ei, batch, Wl1, Wr1, Wl2, Wr2);
    deg_cnt_kernel<<<(EE + 255) / 256, 256>>>(ei, batch);
    scan1_kernel<<<nb, 256>>>();
    gemm_bf16x3_kernel<0><<<gemm_blocks, 128, GEMM_SMEM>>>(
        x, 0, 1, nullptr, nullptr, nullptr, pp, qp);           // profile slot 4
    scan2_kernel<<<1, 512>>>(nb);
    scan3_kernel<<<nb, 256>>>();
    place_kernel<<<(EE + 255) / 256, 256>>>(ei);
    gemm_bf16x3_kernel<1><<<gemm_blocks, 128, GEMM_SMEM>>>(
        nullptr, 2, 3, pp, qp, bl1, pp2, qp2);                 // fused gather + GEMM
    foldW_kernel<<<1, 128>>>(Wl3, Wr3, bl3, Wlin, blin);
    gather2z_kernel<<<NN / 8, 256>>>(pp2, qp2, bl2);
    pool3_kernel<<<nb, 256>>>(batch);
    finalize_kernel<<<1, 128>>>(out);
}

// round 11
// speedup vs baseline: 1.3413x; 1.3413x over previous
#include <cuda_runtime.h>
#include <cstdint>

#define NN 100000
#define EE 1600000
#define DD 128
#define NG 64

// ---------------- scratch (static device globals; no allocation) ----------------
__device__ int      g_ei64, g_b64;
__device__ int      g_degi[NN];
__device__ int      g_start[NN];
__device__ int      g_cursor[NN];
__device__ int      g_bsum[512];
__device__ int      g_cnti[NG];
__device__ int      g_csr[EE];
__device__ float    g_winv[NN];
__device__ float    g_cinv[NG];
__device__ unsigned g_pb[(size_t)NN * 64];    // P packed bf16x2
__device__ unsigned g_qb[(size_t)NN * 64];    // Q packed bf16x2
__device__ float    g_h1[(size_t)NN * DD];
__device__ float    g_z[(size_t)NN * 4];
__device__ unsigned g_wspT[4][2][DD][64];     // pre-split W, transposed [mat][plane][n][k2]
__device__ float    g_Wcl[DD * 2];
__device__ float    g_Wcr[DD * 2];
__device__ float    g_cb[2];
__device__ float    g_acc[NG * 2];

// ---------------- helpers ----------------
__device__ __forceinline__ unsigned pack_bf2(float lo, float hi) {
    unsigned r;
    asm("cvt.rn.bf16x2.f32 %0, %1, %2;" : "=r"(r) : "f"(hi), "f"(lo));
    return r;
}
__device__ __forceinline__ void split2(float x0, float x1, unsigned& p0, unsigned& p1) {
    p0 = pack_bf2(x0, x1);
    float h0 = __uint_as_float(p0 << 16);
    float h1 = __uint_as_float(p0 & 0xFFFF0000u);
    p1 = pack_bf2(x0 - h0, x1 - h1);
}
__device__ __forceinline__ void mma_bf16(float* d, const unsigned* a, const unsigned* b) {
    asm volatile(
        "mma.sync.aligned.m16n8k16.row.col.f32.bf16.bf16.f32 "
        "{%0,%1,%2,%3}, {%4,%5,%6,%7}, {%8,%9}, {%0,%1,%2,%3};"
        : "+f"(d[0]), "+f"(d[1]), "+f"(d[2]), "+f"(d[3])
        : "r"(a[0]), "r"(a[1]), "r"(a[2]), "r"(a[3]), "r"(b[0]), "r"(b[1]));
}
__device__ __forceinline__ void ldsm_x4(unsigned& r0, unsigned& r1, unsigned& r2, unsigned& r3,
                                        unsigned saddr) {
    asm volatile("ldmatrix.sync.aligned.m8n8.x4.shared.b16 {%0,%1,%2,%3}, [%4];"
                 : "=r"(r0), "=r"(r1), "=r"(r2), "=r"(r3) : "r"(saddr));
}
__device__ __forceinline__ void acc_bf2(float4& acc, uint2 v) {
    acc.x += __uint_as_float(v.x << 16);
    acc.y += __uint_as_float(v.x & 0xFFFF0000u);
    acc.z += __uint_as_float(v.y << 16);
    acc.w += __uint_as_float(v.y & 0xFFFF0000u);
}

__device__ __forceinline__ int ld_ei(const void* p, long long i) {
    return g_ei64 ? (int)((const long long*)p)[i] : ((const int*)p)[i];
}
__device__ __forceinline__ int ld_b(const void* p, long long i) {
    return g_b64 ? (int)((const long long*)p)[i] : ((const int*)p)[i];
}

// ---------------- K0: zero + presplit + detect (role-split) ----------------
__global__ void __launch_bounds__(256) init_kernel(const void* ei, const void* batch,
                                                   const float* __restrict__ Wl1,
                                                   const float* __restrict__ Wr1,
                                                   const float* __restrict__ Wl2,
                                                   const float* __restrict__ Wr2) {
    int bid = blockIdx.x;
    if (bid < 391) {
        int i = bid * 256 + threadIdx.x;
        if (i < NN) g_degi[i] = 0;
        if (i < NG) g_cnti[i] = 0;
        if (i < NG * 2) g_acc[i] = 0.0f;
    } else if (bid < 519) {
        int idx = (bid - 391) * 256 + threadIdx.x;
        int mat = idx >> 13;
        int rem = idx & 8191;
        int k2 = rem >> 7;
        int n = rem & 127;
        const float* W = (mat == 0) ? Wl1 : (mat == 1) ? Wr1 : (mat == 2) ? Wl2 : Wr2;
        float w0 = W[(2 * k2) * DD + n];
        float w1 = W[(2 * k2 + 1) * DD + n];
        unsigned p0, p1;
        split2(w0, w1, p0, p1);
        g_wspT[mat][0][n][k2] = p0;
        g_wspT[mat][1][n][k2] = p1;
    } else if (threadIdx.x == 0) {
        const long long* p = (const long long*)ei;
        bool e64 = true;
        #pragma unroll
        for (int i = 0; i < 16; i++) {
            long long v = p[(size_t)i * 99991];
            if (v < 0 || v >= NN) e64 = false;
        }
        g_ei64 = e64 ? 1 : 0;
        const long long* q = (const long long*)batch;
        bool b64 = true;
        #pragma unroll
        for (int i = 0; i < 8; i++) {
            long long v = q[NN / 2 - 1 - i * 37];
            if (v < 0 || v >= NG) b64 = false;
        }
        g_b64 = b64 ? 1 : 0;
    }
}

// ---------------- fused degree + batch histogram ----------------
__global__ void __launch_bounds__(256) deg_cnt_kernel(const void* __restrict__ ei,
                                                      const void* __restrict__ batch) {
    __shared__ int sh[NG];
    if (threadIdx.x < NG) sh[threadIdx.x] = 0;
    __syncthreads();
    int e = blockIdx.x * 256 + threadIdx.x;
    if (e < EE) {
        unsigned d = (unsigned)ld_ei(ei, (long long)EE + e);
        if (d < NN) atomicAdd(&g_degi[d], 1);
    }
    if (e < NN) {
        unsigned g = (unsigned)ld_b(batch, e);
        if (g < NG) atomicAdd(&sh[g], 1);
    }
    __syncthreads();
    if (threadIdx.x < NG && sh[threadIdx.x] != 0) atomicAdd(&g_cnti[threadIdx.x], sh[threadIdx.x]);
}

// ---------------- scans / CSR placement ----------------
__global__ void __launch_bounds__(256) scan1_kernel() {
    __shared__ int sdata[256];
    int t = threadIdx.x;
    int i = blockIdx.x * 256 + t;
    int v = (i < NN) ? g_degi[i] : 0;
    sdata[t] = v;
    __syncthreads();
    #pragma unroll
    for (int off = 1; off < 256; off <<= 1) {
        int x = (t >= off) ? sdata[t - off] : 0;
        __syncthreads();
        sdata[t] += x;
        __syncthreads();
    }
    int incl = sdata[t];
    if (i < NN) g_start[i] = incl - v;
    if (t == 255) g_bsum[blockIdx.x] = incl;
}

__global__ void __launch_bounds__(512) scan2_kernel(int nb) {
    __shared__ int sdata[512];
    int t = threadIdx.x;
    int v = (t < nb) ? g_bsum[t] : 0;
    sdata[t] = v;
    __syncthreads();
    #pragma unroll
    for (int off = 1; off < 512; off <<= 1) {
        int x = (t >= off) ? sdata[t - off] : 0;
        __syncthreads();
        sdata[t] += x;
        __syncthreads();
    }
    if (t < nb) g_bsum[t] = sdata[t] - v;
    if (t < NG) g_cinv[t] = 1.0f / fmaxf((float)g_cnti[t], 1.0f);
}

__global__ void __launch_bounds__(256) scan3_kernel() {
    int i = blockIdx.x * 256 + threadIdx.x;
    if (i >= NN) return;
    int s = g_start[i] + g_bsum[i >> 8];
    g_start[i] = s;
    g_cursor[i] = s;
    g_winv[i] = 1.0f / fmaxf((float)g_degi[i], 1.0f);
}

__global__ void __launch_bounds__(256) place_kernel(const void* __restrict__ ei) {
    int e = blockIdx.x * blockDim.x + threadIdx.x;
    if (e >= EE) return;
    unsigned s = (unsigned)ld_ei(ei, e);
    unsigned d = (unsigned)ld_ei(ei, (long long)EE + e);
    if (s >= NN || d >= NN) return;
    int pos = atomicAdd(&g_cursor[d], 1);
    g_csr[pos] = (int)s;
}

// ---------------- bf16x3 GEMM: cp.async double-buffered B (validated R10) ----------------
extern __shared__ unsigned sm_dyn[];
#define AS_STR 68
#define BS_STR 12
#define GEMM_SMEM ((2 * 128 * AS_STR + 4 * 128 * BS_STR) * 4)

__device__ __forceinline__ void issue_b(const unsigned* __restrict__ WT, int ko2,
                                        unsigned sa0, unsigned sa1, int tid) {
    #pragma unroll
    for (int i = 0; i < 4; i++) {
        int slot = tid + 128 * i;
        int pl = slot >> 8;
        int rem = slot & 255;
        int n = rem >> 1;
        int half = rem & 1;
        const unsigned* src = WT + ((size_t)pl * 128 + n) * 64 + ko2 + half * 4;
        unsigned dst = (pl ? sa1 : sa0) + (unsigned)(n * BS_STR + half * 4) * 4;
        asm volatile("cp.async.cg.shared.global [%0], [%1], 16;" :: "r"(dst), "l"(src));
    }
}

__global__ void __launch_bounds__(128) gemm_bf16x3_kernel(const float* __restrict__ X,
                                                          int matL, int matR,
                                                          unsigned* __restrict__ Pout,
                                                          unsigned* __restrict__ Qout) {
    unsigned* As0 = sm_dyn;
    unsigned* As1 = sm_dyn + 128 * AS_STR;
    unsigned* Bb = sm_dyn + 2 * 128 * AS_STR;

    int tid = threadIdx.x;
    int warp = tid >> 5, lane = tid & 31;
    int g = lane >> 2, t = lane & 3;
    int wm = (warp >> 1) * 64, wn = (warp & 1) * 64;
    int row0 = blockIdx.x * 128;

    unsigned bsa[2][2];
    #pragma unroll
    for (int bf = 0; bf < 2; bf++)
        #pragma unroll
        for (int pl = 0; pl < 2; pl++)
            bsa[bf][pl] = (unsigned)__cvta_generic_to_shared(Bb + (bf * 2 + pl) * 128 * BS_STR);

    const unsigned* WTs[2] = {&g_wspT[matL][0][0][0], &g_wspT[matR][0][0][0]};

    issue_b(WTs[0], 0, bsa[0][0], bsa[0][1], tid);
    asm volatile("cp.async.commit_group;");

    // ---- A phase ----
    #pragma unroll
    for (int i = 0; i < 32; i++) {
        int slot = tid + 128 * i;
        int m = slot >> 5;
        int k4 = (slot & 31) * 4;
        int r = row0 + m;
        float4 av = (r < NN) ? *(const float4*)(X + (size_t)r * DD + k4)
                             : make_float4(0.f, 0.f, 0.f, 0.f);
        unsigned p0, p1, q0, q1;
        split2(av.x, av.y, p0, p1);
        split2(av.z, av.w, q0, q1);
        int k2 = k4 >> 1;
        *(uint2*)&As0[m * AS_STR + k2] = make_uint2(p0, q0);
        *(uint2*)&As1[m * AS_STR + k2] = make_uint2(p1, q1);
    }

    asm volatile("cp.async.wait_group 0;" ::: "memory");
    __syncthreads();

    int arow = (lane & 7) + ((lane & 8) ? 8 : 0);
    int akb = (lane & 16) ? 16 : 0;
    int brow = (lane & 7) + ((lane & 16) ? 8 : 0);
    int bkb = (lane & 8) ? 16 : 0;

    unsigned a0base = (unsigned)__cvta_generic_to_shared(As0) + (wm + arow) * (AS_STR * 4) + akb;
    unsigned a1base = (unsigned)__cvta_generic_to_shared(As1) + (wm + arow) * (AS_STR * 4) + akb;
    unsigned bbase[2][2];
    #pragma unroll
    for (int bf = 0; bf < 2; bf++)
        #pragma unroll
        for (int pl = 0; pl < 2; pl++)
            bbase[bf][pl] = bsa[bf][pl] + (wn + brow) * (BS_STR * 4) + bkb;

    float acc[4][8][4];
    #pragma unroll
    for (int a = 0; a < 4; a++)
        #pragma unroll
        for (int b = 0; b < 8; b++)
            #pragma unroll
            for (int c = 0; c < 4; c++) acc[a][b][c] = 0.0f;

    #pragma unroll
    for (int c = 0; c < 16; c++) {
        const int cur = c & 1;
        if (c < 15) {
            issue_b(WTs[(c + 1) >> 3], ((c + 1) & 7) * 8, bsa[cur ^ 1][0], bsa[cur ^ 1][1], tid);
            asm volatile("cp.async.commit_group;");
        }
        int ko2 = (c & 7) * 8;
        unsigned a0f[4][4], a1f[4][4];
        #pragma unroll
        for (int mt = 0; mt < 4; mt++) {
            unsigned off = mt * 16 * (AS_STR * 4) + ko2 * 4;
            ldsm_x4(a0f[mt][0], a0f[mt][1], a0f[mt][2], a0f[mt][3], a0base + off);
            ldsm_x4(a1f[mt][0], a1f[mt][1], a1f[mt][2], a1f[mt][3], a1base + off);
        }
        #pragma unroll
        for (int ntp = 0; ntp < 4; ntp++) {
            unsigned off = ntp * 16 * (BS_STR * 4);
            unsigned p0r0, p0r1, p0r2, p0r3, p1r0, p1r1, p1r2, p1r3;
            ldsm_x4(p0r0, p0r1, p0r2, p0r3, bbase[cur][0] + off);
            ldsm_x4(p1r0, p1r1, p1r2, p1r3, bbase[cur][1] + off);
            unsigned bh0[2] = {p0r0, p0r1}, bh1[2] = {p0r2, p0r3};
            unsigned bl0[2] = {p1r0, p1r1}, bl1[2] = {p1r2, p1r3};
            #pragma unroll
            for (int mt = 0; mt < 4; mt++) {
                mma_bf16(acc[mt][2 * ntp], a0f[mt], bh0);
                mma_bf16(acc[mt][2 * ntp], a0f[mt], bl0);
                mma_bf16(acc[mt][2 * ntp], a1f[mt], bh0);
                mma_bf16(acc[mt][2 * ntp + 1], a0f[mt], bh1);
                mma_bf16(acc[mt][2 * ntp + 1], a0f[mt], bl1);
                mma_bf16(acc[mt][2 * ntp + 1], a1f[mt], bh1);
            }
        }
        if (c == 7) {
            #pragma unroll
            for (int mt = 0; mt < 4; mt++) {
                #pragma unroll
                for (int nt = 0; nt < 8; nt++) {
                    int r = row0 + wm + mt * 16 + g;
                    int cc = wn + nt * 8 + 2 * t;
                    if (r < NN)
                        Pout[(size_t)r * 64 + (cc >> 1)] = pack_bf2(acc[mt][nt][0], acc[mt][nt][1]);
                    if (r + 8 < NN)
                        Pout[(size_t)(r + 8) * 64 + (cc >> 1)] = pack_bf2(acc[mt][nt][2], acc[mt][nt][3]);
                    acc[mt][nt][0] = acc[mt][nt][1] = acc[mt][nt][2] = acc[mt][nt][3] = 0.0f;
                }
            }
        }
        if (c < 15) {
            asm volatile("cp.async.wait_group 0;" ::: "memory");
            __syncthreads();
        }
    }

    #pragma unroll
    for (int mt = 0; mt < 4; mt++) {
        #pragma unroll
        for (int nt = 0; nt < 8; nt++) {
            int r = row0 + wm + mt * 16 + g;
            int cc = wn + nt * 8 + 2 * t;
            if (r < NN)
                Qout[(size_t)r * 64 + (cc >> 1)] = pack_bf2(acc[mt][nt][0], acc[mt][nt][1]);
            if (r + 8 < NN)
                Qout[(size_t)(r + 8) * 64 + (cc >> 1)] = pack_bf2(acc[mt][nt][2], acc[mt][nt][3]);
        }
    }
}

// ---------------- CSR gather (bf16 P + bf16 Q), warp per node ----------------
__global__ void __launch_bounds__(256) gather_kernel(const unsigned* __restrict__ P,
                                                     const unsigned* __restrict__ Q,
                                                     const float* __restrict__ bias,
                                                     float* __restrict__ H) {
    int node = blockIdx.x * 8 + (threadIdx.x >> 5);
    int lane = threadIdx.x & 31;
    int s = g_start[node];
    int d = g_degi[node];
    float4 acc = make_float4(0.f, 0.f, 0.f, 0.f);
    for (int j = 0; j < d; j++) {
        int src = g_csr[s + j];
        uint2 v = ((const uint2*)(P + (size_t)src * 64))[lane];
        acc_bf2(acc, v);
    }
    float w = g_winv[node];
    float4 q = make_float4(0.f, 0.f, 0.f, 0.f);
    acc_bf2(q, ((const uint2*)(Q + (size_t)node * 64))[lane]);
    float4 b = ((const float4*)bias)[lane];
    float4 o;
    o.x = fmaxf(acc.x * w + q.x + b.x, 0.0f);
    o.y = fmaxf(acc.y * w + q.y + b.y, 0.0f);
    o.z = fmaxf(acc.z * w + q.z + b.z, 0.0f);
    o.w = fmaxf(acc.w * w + q.w + b.w, 0.0f);
    ((float4*)(H + (size_t)node * DD))[lane] = o;
}

// ---------------- layer-2 gather fused with layer-3 projection -> z ----------------
__global__ void __launch_bounds__(256) gather2z_kernel(const unsigned* __restrict__ P,
                                                       const unsigned* __restrict__ Q,
                                                       const float* __restrict__ bias) {
    int node = blockIdx.x * 8 + (threadIdx.x >> 5);
    int lane = threadIdx.x & 31;
    int s = g_start[node];
    int d = g_degi[node];
    float4 acc = make_float4(0.f, 0.f, 0.f, 0.f);
    for (int j = 0; j < d; j++) {
        int src = g_csr[s + j];
        uint2 v = ((const uint2*)(P + (size_t)src * 64))[lane];
        acc_bf2(acc, v);
    }
    float w = g_winv[node];
    float4 q = make_float4(0.f, 0.f, 0.f, 0.f);
    acc_bf2(q, ((const uint2*)(Q + (size_t)node * 64))[lane]);
    float4 b = ((const float4*)bias)[lane];
    float hv[4];
    hv[0] = fmaxf(acc.x * w + q.x + b.x, 0.0f);
    hv[1] = fmaxf(acc.y * w + q.y + b.y, 0.0f);
    hv[2] = fmaxf(acc.z * w + q.z + b.z, 0.0f);
    hv[3] = fmaxf(acc.w * w + q.w + b.w, 0.0f);
    float s0 = 0.f, s1 = 0.f, s2 = 0.f, s3 = 0.f;
    #pragma unroll
    for (int j = 0; j < 4; j++) {
        int k = lane * 4 + j;
        s0 += hv[j] * g_Wcl[k * 2 + 0];
        s1 += hv[j] * g_Wcl[k * 2 + 1];
        s2 += hv[j] * g_Wcr[k * 2 + 0];
        s3 += hv[j] * g_Wcr[k * 2 + 1];
    }
    #pragma unroll
    for (int o = 16; o > 0; o >>= 1) {
        s0 += __shfl_down_sync(0xFFFFFFFFu, s0, o);
        s1 += __shfl_down_sync(0xFFFFFFFFu, s1, o);
        s2 += __shfl_down_sync(0xFFFFFFFFu, s2, o);
        s3 += __shfl_down_sync(0xFFFFFFFFu, s3, o);
    }
    if (lane == 0) ((float4*)g_z)[node] = make_float4(s0, s1, s2, s3);
}

// ---------------- layer-3 fold ----------------
__global__ void foldW_kernel(const float* __restrict__ Wl3, const float* __restrict__ Wr3,
                             const float* __restrict__ bl3, const float* __restrict__ Wlin,
                             const float* __restrict__ blin) {
    int k = threadIdx.x;
    float a0 = 0.f, a1 = 0.f, b0 = 0.f, b1 = 0.f;
    for (int m = 0; m < DD; m++) {
        float wl = Wl3[k * DD + m], wr = Wr3[k * DD + m];
        float l0 = Wlin[m * 2 + 0], l1 = Wlin[m * 2 + 1];
        a0 += wl * l0; a1 += wl * l1;
        b0 += wr * l0; b1 += wr * l1;
    }
    g_Wcl[k * 2 + 0] = a0; g_Wcl[k * 2 + 1] = a1;
    g_Wcr[k * 2 + 0] = b0; g_Wcr[k * 2 + 1] = b1;
    if (k < 2) {
        float cv = blin[k];
        for (int m = 0; m < DD; m++) cv += bl3[m] * Wlin[m * 2 + k];
        g_cb[k] = cv;
    }
}

// ---------------- layer-3 pooled reduction ----------------
__global__ void __launch_bounds__(256) pool3_kernel(const void* __restrict__ batch) {
    __shared__ float sh[NG * 2];
    for (int i = threadIdx.x; i < NG * 2; i += blockDim.x) sh[i] = 0.0f;
    __syncthreads();
    int n = blockIdx.x * 256 + threadIdx.x;
    if (n < NN) {
        int s = g_start[n], d = g_degi[n];
        float s0 = 0.f, s1 = 0.f;
        for (int j = 0; j < d; j++) {
            int src = g_csr[s + j];
            float2 zl = *(const float2*)(g_z + (size_t)src * 4);
            s0 += zl.x; s1 += zl.y;
        }
        float w = g_winv[n];
        unsigned gg = (unsigned)ld_b(batch, n);
        if (gg < NG) {
            float ci = g_cinv[gg];
            float2 zr = *(const float2*)(g_z + (size_t)n * 4 + 2);
            atomicAdd(&sh[gg * 2 + 0], ci * (w * s0 + zr.x));
            atomicAdd(&sh[gg * 2 + 1], ci * (w * s1 + zr.y));
        }
    }
    __syncthreads();
    for (int i = threadIdx.x; i < NG * 2; i += blockDim.x)
        if (sh[i] != 0.0f) atomicAdd(&g_acc[i], sh[i]);
}

__global__ void finalize_kernel(float* __restrict__ out) {
    int t = threadIdx.x;
    if (t < NG * 2) out[t] = g_acc[t] + g_cb[t & 1];
}

// ---------------- host launcher ----------------
extern "C" void kernel_launch(void* const* d_in, const int* in_sizes, int n_in,
                              void* d_out, int out_size) {
    const float* x = (const float*)d_in[0];
    const void* ei = d_in[1];
    const void* batch = d_in[2];
    const float* Wl1 = (const float*)d_in[3];
    const float* bl1 = (const float*)d_in[4];
    const float* Wr1 = (const float*)d_in[5];
    const float* Wl2 = (const float*)d_in[6];
    const float* bl2 = (const float*)d_in[7];
    const float* Wr2 = (const float*)d_in[8];
    const float* Wl3 = (const float*)d_in[9];
    const float* bl3 = (const float*)d_in[10];
    const float* Wr3 = (const float*)d_in[11];
    const float* Wlin = (const float*)d_in[12];
    const float* blin = (const float*)d_in[13];
    float* out = (float*)d_out;

    unsigned *pp = nullptr, *qp = nullptr;
    float* h1p = nullptr;
    cudaGetSymbolAddress((void**)&pp, g_pb);
    cudaGetSymbolAddress((void**)&qp, g_qb);
    cudaGetSymbolAddress((void**)&h1p, g_h1);

    cudaFuncSetAttribute(gemm_bf16x3_kernel,
                         cudaFuncAttributeMaxDynamicSharedMemorySize, GEMM_SMEM);

    const int nb = (NN + 255) / 256;           // 391
    const int gemm_blocks = (NN + 127) / 128;  // 782

    init_kernel<<<520, 256>>>(ei, batch, Wl1, Wr1, Wl2, Wr2);
    deg_cnt_kernel<<<(EE + 255) / 256, 256>>>(ei, batch);
    scan1_kernel<<<nb, 256>>>();
    gemm_bf16x3_kernel<<<gemm_blocks, 128, GEMM_SMEM>>>(x, 0, 1, pp, qp);   // profile slot 4
    scan2_kernel<<<1, 512>>>(nb);
    scan3_kernel<<<nb, 256>>>();
    place_kernel<<<(EE + 255) / 256, 256>>>(ei);
    gather_kernel<<<NN / 8, 256>>>(pp, qp, bl1, h1p);
    gemm_bf16x3_kernel<<<gemm_blocks, 128, GEMM_SMEM>>>(h1p, 2, 3, pp, qp);
    foldW_kernel<<<1, 128>>>(Wl3, Wr3, bl3, Wlin, blin);
    gather2z_kernel<<<NN / 8, 256>>>(pp, qp, bl2);
    pool3_kernel<<<nb, 256>>>(batch);
    finalize_kernel<<<1, 128>>>(out);
}

// round 12
// speedup vs baseline: 1.3462x; 1.0037x over previous
#include <cuda_runtime.h>
#include <cstdint>

#define NN 100000
#define EE 1600000
#define DD 128
#define NG 64

// ---------------- scratch (static device globals; no allocation) ----------------
__device__ int      g_ei64, g_b64;
__device__ int      g_degi[NN];
__device__ int      g_start[NN];
__device__ int      g_cursor[NN];
__device__ int      g_bsum[512];
__device__ int      g_cnti[NG];
__device__ int      g_csr[EE];
__device__ float    g_winv[NN];
__device__ float    g_cinv[NG];
__device__ unsigned g_pb[(size_t)NN * 64];    // P packed bf16x2
__device__ unsigned g_qb[(size_t)NN * 64];    // Q packed bf16x2
__device__ float    g_h1[(size_t)NN * DD];
__device__ float    g_z[(size_t)NN * 4];
__device__ unsigned g_wspT[4][2][DD][64];     // pre-split W, transposed [mat][plane][n][k2]
__device__ float    g_Wcl[DD * 2];
__device__ float    g_Wcr[DD * 2];
__device__ float    g_cb[2];
__device__ float    g_acc[NG * 2];

// ---------------- helpers ----------------
__device__ __forceinline__ unsigned pack_bf2(float lo, float hi) {
    unsigned r;
    asm("cvt.rn.bf16x2.f32 %0, %1, %2;" : "=r"(r) : "f"(hi), "f"(lo));
    return r;
}
__device__ __forceinline__ void split2(float x0, float x1, unsigned& p0, unsigned& p1) {
    p0 = pack_bf2(x0, x1);
    float h0 = __uint_as_float(p0 << 16);
    float h1 = __uint_as_float(p0 & 0xFFFF0000u);
    p1 = pack_bf2(x0 - h0, x1 - h1);
}
__device__ __forceinline__ void mma_bf16(float* d, const unsigned* a, const unsigned* b) {
    asm volatile(
        "mma.sync.aligned.m16n8k16.row.col.f32.bf16.bf16.f32 "
        "{%0,%1,%2,%3}, {%4,%5,%6,%7}, {%8,%9}, {%0,%1,%2,%3};"
        : "+f"(d[0]), "+f"(d[1]), "+f"(d[2]), "+f"(d[3])
        : "r"(a[0]), "r"(a[1]), "r"(a[2]), "r"(a[3]), "r"(b[0]), "r"(b[1]));
}
__device__ __forceinline__ void ldsm_x4(unsigned& r0, unsigned& r1, unsigned& r2, unsigned& r3,
                                        unsigned saddr) {
    asm volatile("ldmatrix.sync.aligned.m8n8.x4.shared.b16 {%0,%1,%2,%3}, [%4];"
                 : "=r"(r0), "=r"(r1), "=r"(r2), "=r"(r3) : "r"(saddr));
}
__device__ __forceinline__ void acc_bf2(float4& acc, uint2 v) {
    acc.x += __uint_as_float(v.x << 16);
    acc.y += __uint_as_float(v.x & 0xFFFF0000u);
    acc.z += __uint_as_float(v.y << 16);
    acc.w += __uint_as_float(v.y & 0xFFFF0000u);
}

__device__ __forceinline__ int ld_ei(const void* p, long long i) {
    return g_ei64 ? (int)((const long long*)p)[i] : ((const int*)p)[i];
}
__device__ __forceinline__ int ld_b(const void* p, long long i) {
    return g_b64 ? (int)((const long long*)p)[i] : ((const int*)p)[i];
}

// ---------------- K0: zero + presplit + detect (role-split) ----------------
__global__ void __launch_bounds__(256) init_kernel(const void* ei, const void* batch,
                                                   const float* __restrict__ Wl1,
                                                   const float* __restrict__ Wr1,
                                                   const float* __restrict__ Wl2,
                                                   const float* __restrict__ Wr2) {
    int bid = blockIdx.x;
    if (bid < 391) {
        int i = bid * 256 + threadIdx.x;
        if (i < NN) g_degi[i] = 0;
        if (i < NG) g_cnti[i] = 0;
        if (i < NG * 2) g_acc[i] = 0.0f;
    } else if (bid < 519) {
        int idx = (bid - 391) * 256 + threadIdx.x;
        int mat = idx >> 13;
        int rem = idx & 8191;
        int k2 = rem >> 7;
        int n = rem & 127;
        const float* W = (mat == 0) ? Wl1 : (mat == 1) ? Wr1 : (mat == 2) ? Wl2 : Wr2;
        float w0 = W[(2 * k2) * DD + n];
        float w1 = W[(2 * k2 + 1) * DD + n];
        unsigned p0, p1;
        split2(w0, w1, p0, p1);
        g_wspT[mat][0][n][k2] = p0;
        g_wspT[mat][1][n][k2] = p1;
    } else if (threadIdx.x == 0) {
        const long long* p = (const long long*)ei;
        bool e64 = true;
        #pragma unroll
        for (int i = 0; i < 16; i++) {
            long long v = p[(size_t)i * 99991];
            if (v < 0 || v >= NN) e64 = false;
        }
        g_ei64 = e64 ? 1 : 0;
        const long long* q = (const long long*)batch;
        bool b64 = true;
        #pragma unroll
        for (int i = 0; i < 8; i++) {
            long long v = q[NN / 2 - 1 - i * 37];
            if (v < 0 || v >= NG) b64 = false;
        }
        g_b64 = b64 ? 1 : 0;
    }
}

// ---------------- fused degree + batch histogram ----------------
__global__ void __launch_bounds__(256) deg_cnt_kernel(const void* __restrict__ ei,
                                                      const void* __restrict__ batch) {
    __shared__ int sh[NG];
    if (threadIdx.x < NG) sh[threadIdx.x] = 0;
    __syncthreads();
    int e = blockIdx.x * 256 + threadIdx.x;
    if (e < EE) {
        unsigned d = (unsigned)ld_ei(ei, (long long)EE + e);
        if (d < NN) atomicAdd(&g_degi[d], 1);
    }
    if (e < NN) {
        unsigned g = (unsigned)ld_b(batch, e);
        if (g < NG) atomicAdd(&sh[g], 1);
    }
    __syncthreads();
    if (threadIdx.x < NG && sh[threadIdx.x] != 0) atomicAdd(&g_cnti[threadIdx.x], sh[threadIdx.x]);
}

// ---------------- scans / CSR placement ----------------
__global__ void __launch_bounds__(256) scan1_kernel() {
    __shared__ int sdata[256];
    int t = threadIdx.x;
    int i = blockIdx.x * 256 + t;
    int v = (i < NN) ? g_degi[i] : 0;
    sdata[t] = v;
    __syncthreads();
    #pragma unroll
    for (int off = 1; off < 256; off <<= 1) {
        int x = (t >= off) ? sdata[t - off] : 0;
        __syncthreads();
        sdata[t] += x;
        __syncthreads();
    }
    int incl = sdata[t];
    if (i < NN) g_start[i] = incl - v;
    if (t == 255) g_bsum[blockIdx.x] = incl;
}

__global__ void __launch_bounds__(512) scan2_kernel(int nb) {
    __shared__ int sdata[512];
    int t = threadIdx.x;
    int v = (t < nb) ? g_bsum[t] : 0;
    sdata[t] = v;
    __syncthreads();
    #pragma unroll
    for (int off = 1; off < 512; off <<= 1) {
        int x = (t >= off) ? sdata[t - off] : 0;
        __syncthreads();
        sdata[t] += x;
        __syncthreads();
    }
    if (t < nb) g_bsum[t] = sdata[t] - v;
    if (t < NG) g_cinv[t] = 1.0f / fmaxf((float)g_cnti[t], 1.0f);
}

__global__ void __launch_bounds__(256) scan3_kernel() {
    int i = blockIdx.x * 256 + threadIdx.x;
    if (i >= NN) return;
    int s = g_start[i] + g_bsum[i >> 8];
    g_start[i] = s;
    g_cursor[i] = s;
    g_winv[i] = 1.0f / fmaxf((float)g_degi[i], 1.0f);
}

__global__ void __launch_bounds__(256) place_kernel(const void* __restrict__ ei) {
    int e = blockIdx.x * blockDim.x + threadIdx.x;
    if (e >= EE) return;
    unsigned s = (unsigned)ld_ei(ei, e);
    unsigned d = (unsigned)ld_ei(ei, (long long)EE + e);
    if (s >= NN || d >= NN) return;
    int pos = atomicAdd(&g_cursor[d], 1);
    g_csr[pos] = (int)s;
}

// ---------------- bf16x3 GEMM: 256 threads, 8 warps, 64x32 warp tiles ----------------
extern __shared__ unsigned sm_dyn[];
#define AS_STR 68
#define BS_STR 12
#define GEMM_SMEM ((2 * 128 * AS_STR + 4 * 128 * BS_STR) * 4)   // 94208 B -> 2 blocks/SM

__device__ __forceinline__ void issue_b(const unsigned* __restrict__ WT, int ko2,
                                        unsigned sa0, unsigned sa1, int tid) {
    #pragma unroll
    for (int i = 0; i < 2; i++) {
        int slot = tid + 256 * i;          // 0..511 uint4 slots
        int pl = slot >> 8;
        int rem = slot & 255;
        int n = rem >> 1;
        int half = rem & 1;
        const unsigned* src = WT + ((size_t)pl * 128 + n) * 64 + ko2 + half * 4;
        unsigned dst = (pl ? sa1 : sa0) + (unsigned)(n * BS_STR + half * 4) * 4;
        asm volatile("cp.async.cg.shared.global [%0], [%1], 16;" :: "r"(dst), "l"(src));
    }
}

__global__ void __launch_bounds__(256, 2) gemm_bf16x3_kernel(const float* __restrict__ X,
                                                             int matL, int matR,
                                                             unsigned* __restrict__ Pout,
                                                             unsigned* __restrict__ Qout) {
    unsigned* As0 = sm_dyn;
    unsigned* As1 = sm_dyn + 128 * AS_STR;
    unsigned* Bb = sm_dyn + 2 * 128 * AS_STR;

    int tid = threadIdx.x;
    int warp = tid >> 5, lane = tid & 31;
    int g = lane >> 2, t = lane & 3;
    int wm = (warp >> 2) * 64;        // 2 warp-rows
    int wn = (warp & 3) * 32;         // 4 warp-cols
    int row0 = blockIdx.x * 128;

    unsigned bsa[2][2];
    #pragma unroll
    for (int bf = 0; bf < 2; bf++)
        #pragma unroll
        for (int pl = 0; pl < 2; pl++)
            bsa[bf][pl] = (unsigned)__cvta_generic_to_shared(Bb + (bf * 2 + pl) * 128 * BS_STR);

    const unsigned* WTs[2] = {&g_wspT[matL][0][0][0], &g_wspT[matR][0][0][0]};

    issue_b(WTs[0], 0, bsa[0][0], bsa[0][1], tid);
    asm volatile("cp.async.commit_group;");

    // ---- A phase: 4096 float4 slots over 256 threads ----
    #pragma unroll
    for (int i = 0; i < 16; i++) {
        int slot = tid + 256 * i;
        int m = slot >> 5;
        int k4 = (slot & 31) * 4;
        int r = row0 + m;
        float4 av = (r < NN) ? *(const float4*)(X + (size_t)r * DD + k4)
                             : make_float4(0.f, 0.f, 0.f, 0.f);
        unsigned p0, p1, q0, q1;
        split2(av.x, av.y, p0, p1);
        split2(av.z, av.w, q0, q1);
        int k2 = k4 >> 1;
        *(uint2*)&As0[m * AS_STR + k2] = make_uint2(p0, q0);
        *(uint2*)&As1[m * AS_STR + k2] = make_uint2(p1, q1);
    }

    asm volatile("cp.async.wait_group 0;" ::: "memory");
    __syncthreads();

    int arow = (lane & 7) + ((lane & 8) ? 8 : 0);
    int akb = (lane & 16) ? 16 : 0;
    int brow = (lane & 7) + ((lane & 16) ? 8 : 0);
    int bkb = (lane & 8) ? 16 : 0;

    unsigned a0base = (unsigned)__cvta_generic_to_shared(As0) + (wm + arow) * (AS_STR * 4) + akb;
    unsigned a1base = (unsigned)__cvta_generic_to_shared(As1) + (wm + arow) * (AS_STR * 4) + akb;
    unsigned bbase[2][2];
    #pragma unroll
    for (int bf = 0; bf < 2; bf++)
        #pragma unroll
        for (int pl = 0; pl < 2; pl++)
            bbase[bf][pl] = bsa[bf][pl] + (wn + brow) * (BS_STR * 4) + bkb;

    float acc[4][4][4];   // [mt][nt][frag]; warp tile 64x32
    #pragma unroll
    for (int a = 0; a < 4; a++)
        #pragma unroll
        for (int b = 0; b < 4; b++)
            #pragma unroll
            for (int c = 0; c < 4; c++) acc[a][b][c] = 0.0f;

    #pragma unroll
    for (int c = 0; c < 16; c++) {
        const int cur = c & 1;
        if (c < 15) {
            issue_b(WTs[(c + 1) >> 3], ((c + 1) & 7) * 8, bsa[cur ^ 1][0], bsa[cur ^ 1][1], tid);
            asm volatile("cp.async.commit_group;");
        }
        int ko2 = (c & 7) * 8;
        unsigned a0f[4][4], a1f[4][4];
        #pragma unroll
        for (int mt = 0; mt < 4; mt++) {
            unsigned off = mt * 16 * (AS_STR * 4) + ko2 * 4;
            ldsm_x4(a0f[mt][0], a0f[mt][1], a0f[mt][2], a0f[mt][3], a0base + off);
            ldsm_x4(a1f[mt][0], a1f[mt][1], a1f[mt][2], a1f[mt][3], a1base + off);
        }
        #pragma unroll
        for (int ntp = 0; ntp < 2; ntp++) {
            unsigned off = ntp * 16 * (BS_STR * 4);
            unsigned p0r0, p0r1, p0r2, p0r3, p1r0, p1r1, p1r2, p1r3;
            ldsm_x4(p0r0, p0r1, p0r2, p0r3, bbase[cur][0] + off);
            ldsm_x4(p1r0, p1r1, p1r2, p1r3, bbase[cur][1] + off);
            unsigned bh0[2] = {p0r0, p0r1}, bh1[2] = {p0r2, p0r3};
            unsigned bl0[2] = {p1r0, p1r1}, bl1[2] = {p1r2, p1r3};
            #pragma unroll
            for (int mt = 0; mt < 4; mt++) {
                mma_bf16(acc[mt][2 * ntp], a0f[mt], bh0);
                mma_bf16(acc[mt][2 * ntp], a0f[mt], bl0);
                mma_bf16(acc[mt][2 * ntp], a1f[mt], bh0);
                mma_bf16(acc[mt][2 * ntp + 1], a0f[mt], bh1);
                mma_bf16(acc[mt][2 * ntp + 1], a0f[mt], bl1);
                mma_bf16(acc[mt][2 * ntp + 1], a1f[mt], bh1);
            }
        }
        if (c == 7) {   // end of phase 0: write P, reset accumulators
            #pragma unroll
            for (int mt = 0; mt < 4; mt++) {
                #pragma unroll
                for (int nt = 0; nt < 4; nt++) {
                    int r = row0 + wm + mt * 16 + g;
                    int cc = wn + nt * 8 + 2 * t;
                    if (r < NN)
                        Pout[(size_t)r * 64 + (cc >> 1)] = pack_bf2(acc[mt][nt][0], acc[mt][nt][1]);
                    if (r + 8 < NN)
                        Pout[(size_t)(r + 8) * 64 + (cc >> 1)] = pack_bf2(acc[mt][nt][2], acc[mt][nt][3]);
                    acc[mt][nt][0] = acc[mt][nt][1] = acc[mt][nt][2] = acc[mt][nt][3] = 0.0f;
                }
            }
        }
        if (c < 15) {
            asm volatile("cp.async.wait_group 0;" ::: "memory");
            __syncthreads();
        }
    }

    // ---- phase-1 epilogue: write Q ----
    #pragma unroll
    for (int mt = 0; mt < 4; mt++) {
        #pragma unroll
        for (int nt = 0; nt < 4; nt++) {
            int r = row0 + wm + mt * 16 + g;
            int cc = wn + nt * 8 + 2 * t;
            if (r < NN)
                Qout[(size_t)r * 64 + (cc >> 1)] = pack_bf2(acc[mt][nt][0], acc[mt][nt][1]);
            if (r + 8 < NN)
                Qout[(size_t)(r + 8) * 64 + (cc >> 1)] = pack_bf2(acc[mt][nt][2], acc[mt][nt][3]);
        }
    }
}

// ---------------- CSR gather (bf16 P + bf16 Q), warp per node ----------------
__global__ void __launch_bounds__(256) gather_kernel(const unsigned* __restrict__ P,
                                                     const unsigned* __restrict__ Q,
                                                     const float* __restrict__ bias,
                                                     float* __restrict__ H) {
    int node = blockIdx.x * 8 + (threadIdx.x >> 5);
    int lane = threadIdx.x & 31;
    int s = g_start[node];
    int d = g_degi[node];
    float4 acc = make_float4(0.f, 0.f, 0.f, 0.f);
    for (int j = 0; j < d; j++) {
        int src = g_csr[s + j];
        uint2 v = ((const uint2*)(P + (size_t)src * 64))[lane];
        acc_bf2(acc, v);
    }
    float w = g_winv[node];
    float4 q = make_float4(0.f, 0.f, 0.f, 0.f);
    acc_bf2(q, ((const uint2*)(Q + (size_t)node * 64))[lane]);
    float4 b = ((const float4*)bias)[lane];
    float4 o;
    o.x = fmaxf(acc.x * w + q.x + b.x, 0.0f);
    o.y = fmaxf(acc.y * w + q.y + b.y, 0.0f);
    o.z = fmaxf(acc.z * w + q.z + b.z, 0.0f);
    o.w = fmaxf(acc.w * w + q.w + b.w, 0.0f);
    ((float4*)(H + (size_t)node * DD))[lane] = o;
}

// ---------------- layer-2 gather fused with layer-3 projection -> z ----------------
__global__ void __launch_bounds__(256) gather2z_kernel(const unsigned* __restrict__ P,
                                                       const unsigned* __restrict__ Q,
                                                       const float* __restrict__ bias) {
    int node = blockIdx.x * 8 + (threadIdx.x >> 5);
    int lane = threadIdx.x & 31;
    int s = g_start[node];
    int d = g_degi[node];
    float4 acc = make_float4(0.f, 0.f, 0.f, 0.f);
    for (int j = 0; j < d; j++) {
        int src = g_csr[s + j];
        uint2 v = ((const uint2*)(P + (size_t)src * 64))[lane];
        acc_bf2(acc, v);
    }
    float w = g_winv[node];
    float4 q = make_float4(0.f, 0.f, 0.f, 0.f);
    acc_bf2(q, ((const uint2*)(Q + (size_t)node * 64))[lane]);
    float4 b = ((const float4*)bias)[lane];
    float hv[4];
    hv[0] = fmaxf(acc.x * w + q.x + b.x, 0.0f);
    hv[1] = fmaxf(acc.y * w + q.y + b.y, 0.0f);
    hv[2] = fmaxf(acc.z * w + q.z + b.z, 0.0f);
    hv[3] = fmaxf(acc.w * w + q.w + b.w, 0.0f);
    float s0 = 0.f, s1 = 0.f, s2 = 0.f, s3 = 0.f;
    #pragma unroll
    for (int j = 0; j < 4; j++) {
        int k = lane * 4 + j;
        s0 += hv[j] * g_Wcl[k * 2 + 0];
        s1 += hv[j] * g_Wcl[k * 2 + 1];
        s2 += hv[j] * g_Wcr[k * 2 + 0];
        s3 += hv[j] * g_Wcr[k * 2 + 1];
    }
    #pragma unroll
    for (int o = 16; o > 0; o >>= 1) {
        s0 += __shfl_down_sync(0xFFFFFFFFu, s0, o);
        s1 += __shfl_down_sync(0xFFFFFFFFu, s1, o);
        s2 += __shfl_down_sync(0xFFFFFFFFu, s2, o);
        s3 += __shfl_down_sync(0xFFFFFFFFu, s3, o);
    }
    if (lane == 0) ((float4*)g_z)[node] = make_float4(s0, s1, s2, s3);
}

// ---------------- layer-3 fold ----------------
__global__ void foldW_kernel(const float* __restrict__ Wl3, const float* __restrict__ Wr3,
                             const float* __restrict__ bl3, const float* __restrict__ Wlin,
                             const float* __restrict__ blin) {
    int k = threadIdx.x;
    float a0 = 0.f, a1 = 0.f, b0 = 0.f, b1 = 0.f;
    for (int m = 0; m < DD; m++) {
        float wl = Wl3[k * DD + m], wr = Wr3[k * DD + m];
        float l0 = Wlin[m * 2 + 0], l1 = Wlin[m * 2 + 1];
        a0 += wl * l0; a1 += wl * l1;
        b0 += wr * l0; b1 += wr * l1;
    }
    g_Wcl[k * 2 + 0] = a0; g_Wcl[k * 2 + 1] = a1;
    g_Wcr[k * 2 + 0] = b0; g_Wcr[k * 2 + 1] = b1;
    if (k < 2) {
        float cv = blin[k];
        for (int m = 0; m < DD; m++) cv += bl3[m] * Wlin[m * 2 + k];
        g_cb[k] = cv;
    }
}

// ---------------- layer-3 pooled reduction ----------------
__global__ void __launch_bounds__(256) pool3_kernel(const void* __restrict__ batch) {
    __shared__ float sh[NG * 2];
    for (int i = threadIdx.x; i < NG * 2; i += blockDim.x) sh[i] = 0.0f;
    __syncthreads();
    int n = blockIdx.x * 256 + threadIdx.x;
    if (n < NN) {
        int s = g_start[n], d = g_degi[n];
        float s0 = 0.f, s1 = 0.f;
        for (int j = 0; j < d; j++) {
            int src = g_csr[s + j];
            float2 zl = *(const float2*)(g_z + (size_t)src * 4);
            s0 += zl.x; s1 += zl.y;
        }
        float w = g_winv[n];
        unsigned gg = (unsigned)ld_b(batch, n);
        if (gg < NG) {
            float ci = g_cinv[gg];
            float2 zr = *(const float2*)(g_z + (size_t)n * 4 + 2);
            atomicAdd(&sh[gg * 2 + 0], ci * (w * s0 + zr.x));
            atomicAdd(&sh[gg * 2 + 1], ci * (w * s1 + zr.y));
        }
    }
    __syncthreads();
    for (int i = threadIdx.x; i < NG * 2; i += blockDim.x)
        if (sh[i] != 0.0f) atomicAdd(&g_acc[i], sh[i]);
}

__global__ void finalize_kernel(float* __restrict__ out) {
    int t = threadIdx.x;
    if (t < NG * 2) out[t] = g_acc[t] + g_cb[t & 1];
}

// ---------------- host launcher ----------------
extern "C" void kernel_launch(void* const* d_in, const int* in_sizes, int n_in,
                              void* d_out, int out_size) {
    const float* x = (const float*)d_in[0];
    const void* ei = d_in[1];
    const void* batch = d_in[2];
    const float* Wl1 = (const float*)d_in[3];
    const float* bl1 = (const float*)d_in[4];
    const float* Wr1 = (const float*)d_in[5];
    const float* Wl2 = (const float*)d_in[6];
    const float* bl2 = (const float*)d_in[7];
    const float* Wr2 = (const float*)d_in[8];
    const float* Wl3 = (const float*)d_in[9];
    const float* bl3 = (const float*)d_in[10];
    const float* Wr3 = (const float*)d_in[11];
    const float* Wlin = (const float*)d_in[12];
    const float* blin = (const float*)d_in[13];
    float* out = (float*)d_out;

    unsigned *pp = nullptr, *qp = nullptr;
    float* h1p = nullptr;
    cudaGetSymbolAddress((void**)&pp, g_pb);
    cudaGetSymbolAddress((void**)&qp, g_qb);
    cudaGetSymbolAddress((void**)&h1p, g_h1);

    cudaFuncSetAttribute(gemm_bf16x3_kernel,
                         cudaFuncAttributeMaxDynamicSharedMemorySize, GEMM_SMEM);

    const int nb = (NN + 255) / 256;           // 391
    const int gemm_blocks = (NN + 127) / 128;  // 782

    init_kernel<<<520, 256>>>(ei, batch, Wl1, Wr1, Wl2, Wr2);
    deg_cnt_kernel<<<(EE + 255) / 256, 256>>>(ei, batch);
    scan1_kernel<<<nb, 256>>>();
    gemm_bf16x3_kernel<<<gemm_blocks, 256, GEMM_SMEM>>>(x, 0, 1, pp, qp);   // profile slot 4
    scan2_kernel<<<1, 512>>>(nb);
    scan3_kernel<<<nb, 256>>>();
    place_kernel<<<(EE + 255) / 256, 256>>>(ei);
    gather_kernel<<<NN / 8, 256>>>(pp, qp, bl1, h1p);
    gemm_bf16x3_kernel<<<gemm_blocks, 256, GEMM_SMEM>>>(h1p, 2, 3, pp, qp);
    foldW_kernel<<<1, 128>>>(Wl3, Wr3, bl3, Wlin, blin);
    gather2z_kernel<<<NN / 8, 256>>>(pp, qp, bl2);
    pool3_kernel<<<nb, 256>>>(batch);
    finalize_kernel<<<1, 128>>>(out);
}

// round 13
// speedup vs baseline: 1.4357x; 1.0665x over previous
#include <cuda_runtime.h>
#include <cstdint>

#define NN 100000
#define EE 1600000
#define DD 128
#define NG 64

// ---------------- scratch (static device globals; no allocation) ----------------
__device__ int      g_ei64, g_b64;
__device__ int      g_degi[NN];
__device__ int      g_start[NN];
__device__ int      g_cursor[NN];
__device__ int      g_bsum[512];
__device__ int      g_cnti[NG];
__device__ int      g_csr[EE];
__device__ float    g_winv[NN];
__device__ float    g_cinv[NG];
__device__ unsigned g_pb[(size_t)NN * 64];    // P packed bf16x2
__device__ unsigned g_qb[(size_t)NN * 64];    // Q packed bf16x2
__device__ float    g_h1[(size_t)NN * DD];
__device__ float    g_z[(size_t)NN * 4];
__device__ unsigned g_wspT[4][2][DD][64];     // pre-split W, transposed [mat][plane][n][k2]
__device__ float    g_Wcl[DD * 2];
__device__ float    g_Wcr[DD * 2];
__device__ float    g_cb[2];
__device__ float    g_acc[NG * 2];

// ---------------- helpers ----------------
__device__ __forceinline__ unsigned pack_bf2(float lo, float hi) {
    unsigned r;
    asm("cvt.rn.bf16x2.f32 %0, %1, %2;" : "=r"(r) : "f"(hi), "f"(lo));
    return r;
}
__device__ __forceinline__ void split2(float x0, float x1, unsigned& p0, unsigned& p1) {
    p0 = pack_bf2(x0, x1);
    float h0 = __uint_as_float(p0 << 16);
    float h1 = __uint_as_float(p0 & 0xFFFF0000u);
    p1 = pack_bf2(x0 - h0, x1 - h1);
}
__device__ __forceinline__ void mma_bf16(float* d, const unsigned* a, const unsigned* b) {
    asm volatile(
        "mma.sync.aligned.m16n8k16.row.col.f32.bf16.bf16.f32 "
        "{%0,%1,%2,%3}, {%4,%5,%6,%7}, {%8,%9}, {%0,%1,%2,%3};"
        : "+f"(d[0]), "+f"(d[1]), "+f"(d[2]), "+f"(d[3])
        : "r"(a[0]), "r"(a[1]), "r"(a[2]), "r"(a[3]), "r"(b[0]), "r"(b[1]));
}
__device__ __forceinline__ void ldsm_x4(unsigned& r0, unsigned& r1, unsigned& r2, unsigned& r3,
                                        unsigned saddr) {
    asm volatile("ldmatrix.sync.aligned.m8n8.x4.shared.b16 {%0,%1,%2,%3}, [%4];"
                 : "=r"(r0), "=r"(r1), "=r"(r2), "=r"(r3) : "r"(saddr));
}
__device__ __forceinline__ void acc_bf2(float4& acc, uint2 v) {
    acc.x += __uint_as_float(v.x << 16);
    acc.y += __uint_as_float(v.x & 0xFFFF0000u);
    acc.z += __uint_as_float(v.y << 16);
    acc.w += __uint_as_float(v.y & 0xFFFF0000u);
}

__device__ __forceinline__ int ld_ei(const void* p, long long i) {
    return g_ei64 ? (int)((const long long*)p)[i] : ((const int*)p)[i];
}
__device__ __forceinline__ int ld_b(const void* p, long long i) {
    return g_b64 ? (int)((const long long*)p)[i] : ((const int*)p)[i];
}

// ---------------- K0: zero + presplit + detect (role-split) ----------------
__global__ void __launch_bounds__(256) init_kernel(const void* ei, const void* batch,
                                                   const float* __restrict__ Wl1,
                                                   const float* __restrict__ Wr1,
                                                   const float* __restrict__ Wl2,
                                                   const float* __restrict__ Wr2) {
    int bid = blockIdx.x;
    if (bid < 391) {
        int i = bid * 256 + threadIdx.x;
        if (i < NN) g_degi[i] = 0;
        if (i < NG) g_cnti[i] = 0;
        if (i < NG * 2) g_acc[i] = 0.0f;
    } else if (bid < 519) {
        int idx = (bid - 391) * 256 + threadIdx.x;
        int mat = idx >> 13;
        int rem = idx & 8191;
        int k2 = rem >> 7;
        int n = rem & 127;
        const float* W = (mat == 0) ? Wl1 : (mat == 1) ? Wr1 : (mat == 2) ? Wl2 : Wr2;
        float w0 = W[(2 * k2) * DD + n];
        float w1 = W[(2 * k2 + 1) * DD + n];
        unsigned p0, p1;
        split2(w0, w1, p0, p1);
        g_wspT[mat][0][n][k2] = p0;
        g_wspT[mat][1][n][k2] = p1;
    } else if (threadIdx.x == 0) {
        const long long* p = (const long long*)ei;
        bool e64 = true;
        #pragma unroll
        for (int i = 0; i < 16; i++) {
            long long v = p[(size_t)i * 99991];
            if (v < 0 || v >= NN) e64 = false;
        }
        g_ei64 = e64 ? 1 : 0;
        const long long* q = (const long long*)batch;
        bool b64 = true;
        #pragma unroll
        for (int i = 0; i < 8; i++) {
            long long v = q[NN / 2 - 1 - i * 37];
            if (v < 0 || v >= NG) b64 = false;
        }
        g_b64 = b64 ? 1 : 0;
    }
}

// ---------------- fused degree + batch histogram ----------------
__global__ void __launch_bounds__(256) deg_cnt_kernel(const void* __restrict__ ei,
                                                      const void* __restrict__ batch) {
    __shared__ int sh[NG];
    if (threadIdx.x < NG) sh[threadIdx.x] = 0;
    __syncthreads();
    int e = blockIdx.x * 256 + threadIdx.x;
    if (e < EE) {
        unsigned d = (unsigned)ld_ei(ei, (long long)EE + e);
        if (d < NN) atomicAdd(&g_degi[d], 1);
    }
    if (e < NN) {
        unsigned g = (unsigned)ld_b(batch, e);
        if (g < NG) atomicAdd(&sh[g], 1);
    }
    __syncthreads();
    if (threadIdx.x < NG && sh[threadIdx.x] != 0) atomicAdd(&g_cnti[threadIdx.x], sh[threadIdx.x]);
}

// ---------------- scans / CSR placement ----------------
__global__ void __launch_bounds__(256) scan1_kernel() {
    __shared__ int sdata[256];
    int t = threadIdx.x;
    int i = blockIdx.x * 256 + t;
    int v = (i < NN) ? g_degi[i] : 0;
    sdata[t] = v;
    __syncthreads();
    #pragma unroll
    for (int off = 1; off < 256; off <<= 1) {
        int x = (t >= off) ? sdata[t - off] : 0;
        __syncthreads();
        sdata[t] += x;
        __syncthreads();
    }
    int incl = sdata[t];
    if (i < NN) g_start[i] = incl - v;
    if (t == 255) g_bsum[blockIdx.x] = incl;
}

__global__ void __launch_bounds__(512) scan2_kernel(int nb) {
    __shared__ int sdata[512];
    int t = threadIdx.x;
    int v = (t < nb) ? g_bsum[t] : 0;
    sdata[t] = v;
    __syncthreads();
    #pragma unroll
    for (int off = 1; off < 512; off <<= 1) {
        int x = (t >= off) ? sdata[t - off] : 0;
        __syncthreads();
        sdata[t] += x;
        __syncthreads();
    }
    if (t < nb) g_bsum[t] = sdata[t] - v;
    if (t < NG) g_cinv[t] = 1.0f / fmaxf((float)g_cnti[t], 1.0f);
}

__global__ void __launch_bounds__(256) scan3_kernel() {
    int i = blockIdx.x * 256 + threadIdx.x;
    if (i >= NN) return;
    int s = g_start[i] + g_bsum[i >> 8];
    g_start[i] = s;
    g_cursor[i] = s;
    g_winv[i] = 1.0f / fmaxf((float)g_degi[i], 1.0f);
}

__global__ void __launch_bounds__(256) place_kernel(const void* __restrict__ ei) {
    int e = blockIdx.x * blockDim.x + threadIdx.x;
    if (e >= EE) return;
    unsigned s = (unsigned)ld_ei(ei, e);
    unsigned d = (unsigned)ld_ei(ei, (long long)EE + e);
    if (s >= NN || d >= NN) return;
    int pos = atomicAdd(&g_cursor[d], 1);
    g_csr[pos] = (int)s;
}

// ---------------- asymmetric bf16x2 GEMM: A single bf16 plane, W hi+lo planes ----------------
// 256 threads, 8 warps (2x4 grid, warp tile 64x32), block tile 128x128.
extern __shared__ unsigned sm_dyn[];
#define AS_STR 68
#define BS_STR 12
#define GEMM_SMEM ((128 * AS_STR + 4 * 128 * BS_STR) * 4)   // 59392 B

__device__ __forceinline__ void issue_b(const unsigned* __restrict__ WT, int ko2,
                                        unsigned sa0, unsigned sa1, int tid) {
    #pragma unroll
    for (int i = 0; i < 2; i++) {
        int slot = tid + 256 * i;          // 0..511 uint4 slots
        int pl = slot >> 8;
        int rem = slot & 255;
        int n = rem >> 1;
        int half = rem & 1;
        const unsigned* src = WT + ((size_t)pl * 128 + n) * 64 + ko2 + half * 4;
        unsigned dst = (pl ? sa1 : sa0) + (unsigned)(n * BS_STR + half * 4) * 4;
        asm volatile("cp.async.cg.shared.global [%0], [%1], 16;" :: "r"(dst), "l"(src));
    }
}

__global__ void __launch_bounds__(256, 2) gemm_bf16x2_kernel(const float* __restrict__ X,
                                                             int matL, int matR,
                                                             unsigned* __restrict__ Pout,
                                                             unsigned* __restrict__ Qout) {
    unsigned* As0 = sm_dyn;                       // [128][AS_STR], single plane
    unsigned* Bb = sm_dyn + 128 * AS_STR;

    int tid = threadIdx.x;
    int warp = tid >> 5, lane = tid & 31;
    int g = lane >> 2, t = lane & 3;
    int wm = (warp >> 2) * 64;
    int wn = (warp & 3) * 32;
    int row0 = blockIdx.x * 128;

    unsigned bsa[2][2];
    #pragma unroll
    for (int bf = 0; bf < 2; bf++)
        #pragma unroll
        for (int pl = 0; pl < 2; pl++)
            bsa[bf][pl] = (unsigned)__cvta_generic_to_shared(Bb + (bf * 2 + pl) * 128 * BS_STR);

    const unsigned* WTs[2] = {&g_wspT[matL][0][0][0], &g_wspT[matR][0][0][0]};

    issue_b(WTs[0], 0, bsa[0][0], bsa[0][1], tid);
    asm volatile("cp.async.commit_group;");

    // ---- A phase: pack fp32 -> single bf16 plane ----
    #pragma unroll
    for (int i = 0; i < 16; i++) {
        int slot = tid + 256 * i;
        int m = slot >> 5;
        int k4 = (slot & 31) * 4;
        int r = row0 + m;
        float4 av = (r < NN) ? *(const float4*)(X + (size_t)r * DD + k4)
                             : make_float4(0.f, 0.f, 0.f, 0.f);
        unsigned p0 = pack_bf2(av.x, av.y);
        unsigned q0 = pack_bf2(av.z, av.w);
        int k2 = k4 >> 1;
        *(uint2*)&As0[m * AS_STR + k2] = make_uint2(p0, q0);
    }

    asm volatile("cp.async.wait_group 0;" ::: "memory");
    __syncthreads();

    int arow = (lane & 7) + ((lane & 8) ? 8 : 0);
    int akb = (lane & 16) ? 16 : 0;
    int brow = (lane & 7) + ((lane & 16) ? 8 : 0);
    int bkb = (lane & 8) ? 16 : 0;

    unsigned a0base = (unsigned)__cvta_generic_to_shared(As0) + (wm + arow) * (AS_STR * 4) + akb;
    unsigned bbase[2][2];
    #pragma unroll
    for (int bf = 0; bf < 2; bf++)
        #pragma unroll
        for (int pl = 0; pl < 2; pl++)
            bbase[bf][pl] = bsa[bf][pl] + (wn + brow) * (BS_STR * 4) + bkb;

    float acc[4][4][4];
    #pragma unroll
    for (int a = 0; a < 4; a++)
        #pragma unroll
        for (int b = 0; b < 4; b++)
            #pragma unroll
            for (int c = 0; c < 4; c++) acc[a][b][c] = 0.0f;

    #pragma unroll
    for (int c = 0; c < 16; c++) {
        const int cur = c & 1;
        if (c < 15) {
            issue_b(WTs[(c + 1) >> 3], ((c + 1) & 7) * 8, bsa[cur ^ 1][0], bsa[cur ^ 1][1], tid);
            asm volatile("cp.async.commit_group;");
        }
        int ko2 = (c & 7) * 8;
        unsigned a0f[4][4];
        #pragma unroll
        for (int mt = 0; mt < 4; mt++) {
            unsigned off = mt * 16 * (AS_STR * 4) + ko2 * 4;
            ldsm_x4(a0f[mt][0], a0f[mt][1], a0f[mt][2], a0f[mt][3], a0base + off);
        }
        #pragma unroll
        for (int ntp = 0; ntp < 2; ntp++) {
            unsigned off = ntp * 16 * (BS_STR * 4);
            unsigned p0r0, p0r1, p0r2, p0r3, p1r0, p1r1, p1r2, p1r3;
            ldsm_x4(p0r0, p0r1, p0r2, p0r3, bbase[cur][0] + off);
            ldsm_x4(p1r0, p1r1, p1r2, p1r3, bbase[cur][1] + off);
            unsigned bh0[2] = {p0r0, p0r1}, bh1[2] = {p0r2, p0r3};
            unsigned bl0[2] = {p1r0, p1r1}, bl1[2] = {p1r2, p1r3};
            #pragma unroll
            for (int mt = 0; mt < 4; mt++) {
                mma_bf16(acc[mt][2 * ntp], a0f[mt], bh0);
                mma_bf16(acc[mt][2 * ntp], a0f[mt], bl0);
                mma_bf16(acc[mt][2 * ntp + 1], a0f[mt], bh1);
                mma_bf16(acc[mt][2 * ntp + 1], a0f[mt], bl1);
            }
        }
        if (c == 7) {   // end of phase 0: write P, reset accumulators
            #pragma unroll
            for (int mt = 0; mt < 4; mt++) {
                #pragma unroll
                for (int nt = 0; nt < 4; nt++) {
                    int r = row0 + wm + mt * 16 + g;
                    int cc = wn + nt * 8 + 2 * t;
                    if (r < NN)
                        Pout[(size_t)r * 64 + (cc >> 1)] = pack_bf2(acc[mt][nt][0], acc[mt][nt][1]);
                    if (r + 8 < NN)
                        Pout[(size_t)(r + 8) * 64 + (cc >> 1)] = pack_bf2(acc[mt][nt][2], acc[mt][nt][3]);
                    acc[mt][nt][0] = acc[mt][nt][1] = acc[mt][nt][2] = acc[mt][nt][3] = 0.0f;
                }
            }
        }
        if (c < 15) {
            asm volatile("cp.async.wait_group 0;" ::: "memory");
            __syncthreads();
        }
    }

    // ---- phase-1 epilogue: write Q ----
    #pragma unroll
    for (int mt = 0; mt < 4; mt++) {
        #pragma unroll
        for (int nt = 0; nt < 4; nt++) {
            int r = row0 + wm + mt * 16 + g;
            int cc = wn + nt * 8 + 2 * t;
            if (r < NN)
                Qout[(size_t)r * 64 + (cc >> 1)] = pack_bf2(acc[mt][nt][0], acc[mt][nt][1]);
            if (r + 8 < NN)
                Qout[(size_t)(r + 8) * 64 + (cc >> 1)] = pack_bf2(acc[mt][nt][2], acc[mt][nt][3]);
        }
    }
}

// ---------------- CSR gather (bf16 P + bf16 Q), warp per node ----------------
__global__ void __launch_bounds__(256) gather_kernel(const unsigned* __restrict__ P,
                                                     const unsigned* __restrict__ Q,
                                                     const float* __restrict__ bias,
                                                     float* __restrict__ H) {
    int node = blockIdx.x * 8 + (threadIdx.x >> 5);
    int lane = threadIdx.x & 31;
    int s = g_start[node];
    int d = g_degi[node];
    float4 acc = make_float4(0.f, 0.f, 0.f, 0.f);
    for (int j = 0; j < d; j++) {
        int src = g_csr[s + j];
        uint2 v = ((const uint2*)(P + (size_t)src * 64))[lane];
        acc_bf2(acc, v);
    }
    float w = g_winv[node];
    float4 q = make_float4(0.f, 0.f, 0.f, 0.f);
    acc_bf2(q, ((const uint2*)(Q + (size_t)node * 64))[lane]);
    float4 b = ((const float4*)bias)[lane];
    float4 o;
    o.x = fmaxf(acc.x * w + q.x + b.x, 0.0f);
    o.y = fmaxf(acc.y * w + q.y + b.y, 0.0f);
    o.z = fmaxf(acc.z * w + q.z + b.z, 0.0f);
    o.w = fmaxf(acc.w * w + q.w + b.w, 0.0f);
    ((float4*)(H + (size_t)node * DD))[lane] = o;
}

// ---------------- layer-2 gather fused with layer-3 projection -> z ----------------
__global__ void __launch_bounds__(256) gather2z_kernel(const unsigned* __restrict__ P,
                                                       const unsigned* __restrict__ Q,
                                                       const float* __restrict__ bias) {
    int node = blockIdx.x * 8 + (threadIdx.x >> 5);
    int lane = threadIdx.x & 31;
    int s = g_start[node];
    int d = g_degi[node];
    float4 acc = make_float4(0.f, 0.f, 0.f, 0.f);
    for (int j = 0; j < d; j++) {
        int src = g_csr[s + j];
        uint2 v = ((const uint2*)(P + (size_t)src * 64))[lane];
        acc_bf2(acc, v);
    }
    float w = g_winv[node];
    float4 q = make_float4(0.f, 0.f, 0.f, 0.f);
    acc_bf2(q, ((const uint2*)(Q + (size_t)node * 64))[lane]);
    float4 b = ((const float4*)bias)[lane];
    float hv[4];
    hv[0] = fmaxf(acc.x * w + q.x + b.x, 0.0f);
    hv[1] = fmaxf(acc.y * w + q.y + b.y, 0.0f);
    hv[2] = fmaxf(acc.z * w + q.z + b.z, 0.0f);
    hv[3] = fmaxf(acc.w * w + q.w + b.w, 0.0f);
    float s0 = 0.f, s1 = 0.f, s2 = 0.f, s3 = 0.f;
    #pragma unroll
    for (int j = 0; j < 4; j++) {
        int k = lane * 4 + j;
        s0 += hv[j] * g_Wcl[k * 2 + 0];
        s1 += hv[j] * g_Wcl[k * 2 + 1];
        s2 += hv[j] * g_Wcr[k * 2 + 0];
        s3 += hv[j] * g_Wcr[k * 2 + 1];
    }
    #pragma unroll
    for (int o = 16; o > 0; o >>= 1) {
        s0 += __shfl_down_sync(0xFFFFFFFFu, s0, o);
        s1 += __shfl_down_sync(0xFFFFFFFFu, s1, o);
        s2 += __shfl_down_sync(0xFFFFFFFFu, s2, o);
        s3 += __shfl_down_sync(0xFFFFFFFFu, s3, o);
    }
    if (lane == 0) ((float4*)g_z)[node] = make_float4(s0, s1, s2, s3);
}

// ---------------- layer-3 fold ----------------
__global__ void foldW_kernel(const float* __restrict__ Wl3, const float* __restrict__ Wr3,
                             const float* __restrict__ bl3, const float* __restrict__ Wlin,
                             const float* __restrict__ blin) {
    int k = threadIdx.x;
    float a0 = 0.f, a1 = 0.f, b0 = 0.f, b1 = 0.f;
    for (int m = 0; m < DD; m++) {
        float wl = Wl3[k * DD + m], wr = Wr3[k * DD + m];
        float l0 = Wlin[m * 2 + 0], l1 = Wlin[m * 2 + 1];
        a0 += wl * l0; a1 += wl * l1;
        b0 += wr * l0; b1 += wr * l1;
    }
    g_Wcl[k * 2 + 0] = a0; g_Wcl[k * 2 + 1] = a1;
    g_Wcr[k * 2 + 0] = b0; g_Wcr[k * 2 + 1] = b1;
    if (k < 2) {
        float cv = blin[k];
        for (int m = 0; m < DD; m++) cv += bl3[m] * Wlin[m * 2 + k];
        g_cb[k] = cv;
    }
}

// ---------------- layer-3 pooled reduction ----------------
__global__ void __launch_bounds__(256) pool3_kernel(const void* __restrict__ batch) {
    __shared__ float sh[NG * 2];
    for (int i = threadIdx.x; i < NG * 2; i += blockDim.x) sh[i] = 0.0f;
    __syncthreads();
    int n = blockIdx.x * 256 + threadIdx.x;
    if (n < NN) {
        int s = g_start[n], d = g_degi[n];
        float s0 = 0.f, s1 = 0.f;
        for (int j = 0; j < d; j++) {
            int src = g_csr[s + j];
            float2 zl = *(const float2*)(g_z + (size_t)src * 4);
            s0 += zl.x; s1 += zl.y;
        }
        float w = g_winv[n];
        unsigned gg = (unsigned)ld_b(batch, n);
        if (gg < NG) {
            float ci = g_cinv[gg];
            float2 zr = *(const float2*)(g_z + (size_t)n * 4 + 2);
            atomicAdd(&sh[gg * 2 + 0], ci * (w * s0 + zr.x));
            atomicAdd(&sh[gg * 2 + 1], ci * (w * s1 + zr.y));
        }
    }
    __syncthreads();
    for (int i = threadIdx.x; i < NG * 2; i += blockDim.x)
        if (sh[i] != 0.0f) atomicAdd(&g_acc[i], sh[i]);
}

__global__ void finalize_kernel(float* __restrict__ out) {
    int t = threadIdx.x;
    if (t < NG * 2) out[t] = g_acc[t] + g_cb[t & 1];
}

// ---------------- host launcher ----------------
extern "C" void kernel_launch(void* const* d_in, const int* in_sizes, int n_in,
                              void* d_out, int out_size) {
    const float* x = (const float*)d_in[0];
    const void* ei = d_in[1];
    const void* batch = d_in[2];
    const float* Wl1 = (const float*)d_in[3];
    const float* bl1 = (const float*)d_in[4];
    const float* Wr1 = (const float*)d_in[5];
    const float* Wl2 = (const float*)d_in[6];
    const float* bl2 = (const float*)d_in[7];
    const float* Wr2 = (const float*)d_in[8];
    const float* Wl3 = (const float*)d_in[9];
    const float* bl3 = (const float*)d_in[10];
    const float* Wr3 = (const float*)d_in[11];
    const float* Wlin = (const float*)d_in[12];
    const float* blin = (const float*)d_in[13];
    float* out = (float*)d_out;

    unsigned *pp = nullptr, *qp = nullptr;
    float* h1p = nullptr;
    cudaGetSymbolAddress((void**)&pp, g_pb);
    cudaGetSymbolAddress((void**)&qp, g_qb);
    cudaGetSymbolAddress((void**)&h1p, g_h1);

    cudaFuncSetAttribute(gemm_bf16x2_kernel,
                         cudaFuncAttributeMaxDynamicSharedMemorySize, GEMM_SMEM);

    const int nb = (NN + 255) / 256;           // 391
    const int gemm_blocks = (NN + 127) / 128;  // 782

    init_kernel<<<520, 256>>>(ei, batch, Wl1, Wr1, Wl2, Wr2);
    deg_cnt_kernel<<<(EE + 255) / 256, 256>>>(ei, batch);
    scan1_kernel<<<nb, 256>>>();
    gemm_bf16x2_kernel<<<gemm_blocks, 256, GEMM_SMEM>>>(x, 0, 1, pp, qp);   // profile slot 4
    scan2_kernel<<<1, 512>>>(nb);
    scan3_kernel<<<nb, 256>>>();
    place_kernel<<<(EE + 255) / 256, 256>>>(ei);
    gather_kernel<<<NN / 8, 256>>>(pp, qp, bl1, h1p);
    gemm_bf16x2_kernel<<<gemm_blocks, 256, GEMM_SMEM>>>(h1p, 2, 3, pp, qp);
    foldW_kernel<<<1, 128>>>(Wl3, Wr3, bl3, Wlin, blin);
    gather2z_kernel<<<NN / 8, 256>>>(pp, qp, bl2);
    pool3_kernel<<<nb, 256>>>(batch);
    finalize_kernel<<<1, 128>>>(out);
}

// round 14
// speedup vs baseline: 1.4462x; 1.0073x over previous
#include <cuda_runtime.h>
#include <cstdint>

#define NN 100000
#define EE 1600000
#define DD 128
#define NG 64

// ---------------- scratch (static device globals; no allocation) ----------------
__device__ int      g_ei64, g_b64;
__device__ int      g_degi[NN];
__device__ int      g_start[NN];
__device__ int      g_cursor[NN];
__device__ int      g_bsum[512];
__device__ int      g_cnti[NG];
__device__ int      g_csr[EE];
__device__ float    g_winv[NN];
__device__ float    g_cinv[NG];
__device__ unsigned g_pb[(size_t)NN * 64];    // P packed bf16x2
__device__ unsigned g_qb[(size_t)NN * 64];    // Q packed bf16x2
__device__ float    g_h1[(size_t)NN * DD];
__device__ float    g_z[(size_t)NN * 4];
__device__ unsigned g_wspT[4][2][DD][64];     // pre-split W, transposed [mat][plane][n][k2]
__device__ float    g_Wcl[DD * 2];
__device__ float    g_Wcr[DD * 2];
__device__ float    g_cb[2];
__device__ float    g_acc[NG * 2];

// ---------------- helpers ----------------
__device__ __forceinline__ unsigned pack_bf2(float lo, float hi) {
    unsigned r;
    asm("cvt.rn.bf16x2.f32 %0, %1, %2;" : "=r"(r) : "f"(hi), "f"(lo));
    return r;
}
__device__ __forceinline__ void split2(float x0, float x1, unsigned& p0, unsigned& p1) {
    p0 = pack_bf2(x0, x1);
    float h0 = __uint_as_float(p0 << 16);
    float h1 = __uint_as_float(p0 & 0xFFFF0000u);
    p1 = pack_bf2(x0 - h0, x1 - h1);
}
__device__ __forceinline__ void mma_bf16(float* d, const unsigned* a, const unsigned* b) {
    asm volatile(
        "mma.sync.aligned.m16n8k16.row.col.f32.bf16.bf16.f32 "
        "{%0,%1,%2,%3}, {%4,%5,%6,%7}, {%8,%9}, {%0,%1,%2,%3};"
        : "+f"(d[0]), "+f"(d[1]), "+f"(d[2]), "+f"(d[3])
        : "r"(a[0]), "r"(a[1]), "r"(a[2]), "r"(a[3]), "r"(b[0]), "r"(b[1]));
}
__device__ __forceinline__ void ldsm_x4(unsigned& r0, unsigned& r1, unsigned& r2, unsigned& r3,
                                        unsigned saddr) {
    asm volatile("ldmatrix.sync.aligned.m8n8.x4.shared.b16 {%0,%1,%2,%3}, [%4];"
                 : "=r"(r0), "=r"(r1), "=r"(r2), "=r"(r3) : "r"(saddr));
}
__device__ __forceinline__ void acc_bf2(float4& acc, uint2 v) {
    acc.x += __uint_as_float(v.x << 16);
    acc.y += __uint_as_float(v.x & 0xFFFF0000u);
    acc.z += __uint_as_float(v.y << 16);
    acc.w += __uint_as_float(v.y & 0xFFFF0000u);
}

__device__ __forceinline__ int ld_ei(const void* p, long long i) {
    return g_ei64 ? (int)((const long long*)p)[i] : ((const int*)p)[i];
}
__device__ __forceinline__ int ld_b(const void* p, long long i) {
    return g_b64 ? (int)((const long long*)p)[i] : ((const int*)p)[i];
}

// ---------------- K0: zero + presplit + detect (role-split) ----------------
__global__ void __launch_bounds__(256) init_kernel(const void* ei, const void* batch,
                                                   const float* __restrict__ Wl1,
                                                   const float* __restrict__ Wr1,
                                                   const float* __restrict__ Wl2,
                                                   const float* __restrict__ Wr2) {
    int bid = blockIdx.x;
    if (bid < 391) {
        int i = bid * 256 + threadIdx.x;
        if (i < NN) g_degi[i] = 0;
        if (i < NG) g_cnti[i] = 0;
        if (i < NG * 2) g_acc[i] = 0.0f;
    } else if (bid < 519) {
        int idx = (bid - 391) * 256 + threadIdx.x;
        int mat = idx >> 13;
        int rem = idx & 8191;
        int k2 = rem >> 7;
        int n = rem & 127;
        const float* W = (mat == 0) ? Wl1 : (mat == 1) ? Wr1 : (mat == 2) ? Wl2 : Wr2;
        float w0 = W[(2 * k2) * DD + n];
        float w1 = W[(2 * k2 + 1) * DD + n];
        unsigned p0, p1;
        split2(w0, w1, p0, p1);
        g_wspT[mat][0][n][k2] = p0;
        g_wspT[mat][1][n][k2] = p1;
    } else if (threadIdx.x == 0) {
        const long long* p = (const long long*)ei;
        bool e64 = true;
        #pragma unroll
        for (int i = 0; i < 16; i++) {
            long long v = p[(size_t)i * 99991];
            if (v < 0 || v >= NN) e64 = false;
        }
        g_ei64 = e64 ? 1 : 0;
        const long long* q = (const long long*)batch;
        bool b64 = true;
        #pragma unroll
        for (int i = 0; i < 8; i++) {
            long long v = q[NN / 2 - 1 - i * 37];
            if (v < 0 || v >= NG) b64 = false;
        }
        g_b64 = b64 ? 1 : 0;
    }
}

// ---------------- fused degree + batch histogram ----------------
__global__ void __launch_bounds__(256) deg_cnt_kernel(const void* __restrict__ ei,
                                                      const void* __restrict__ batch) {
    __shared__ int sh[NG];
    if (threadIdx.x < NG) sh[threadIdx.x] = 0;
    __syncthreads();
    int e = blockIdx.x * 256 + threadIdx.x;
    if (e < EE) {
        unsigned d = (unsigned)ld_ei(ei, (long long)EE + e);
        if (d < NN) atomicAdd(&g_degi[d], 1);
    }
    if (e < NN) {
        unsigned g = (unsigned)ld_b(batch, e);
        if (g < NG) atomicAdd(&sh[g], 1);
    }
    __syncthreads();
    if (threadIdx.x < NG && sh[threadIdx.x] != 0) atomicAdd(&g_cnti[threadIdx.x], sh[threadIdx.x]);
}

// ---------------- scans / CSR placement ----------------
__global__ void __launch_bounds__(256) scan1_kernel() {
    __shared__ int sdata[256];
    int t = threadIdx.x;
    int i = blockIdx.x * 256 + t;
    int v = (i < NN) ? g_degi[i] : 0;
    sdata[t] = v;
    __syncthreads();
    #pragma unroll
    for (int off = 1; off < 256; off <<= 1) {
        int x = (t >= off) ? sdata[t - off] : 0;
        __syncthreads();
        sdata[t] += x;
        __syncthreads();
    }
    int incl = sdata[t];
    if (i < NN) g_start[i] = incl - v;
    if (t == 255) g_bsum[blockIdx.x] = incl;
}

__global__ void __launch_bounds__(512) scan2_kernel(int nb) {
    __shared__ int sdata[512];
    int t = threadIdx.x;
    int v = (t < nb) ? g_bsum[t] : 0;
    sdata[t] = v;
    __syncthreads();
    #pragma unroll
    for (int off = 1; off < 512; off <<= 1) {
        int x = (t >= off) ? sdata[t - off] : 0;
        __syncthreads();
        sdata[t] += x;
        __syncthreads();
    }
    if (t < nb) g_bsum[t] = sdata[t] - v;
    if (t < NG) g_cinv[t] = 1.0f / fmaxf((float)g_cnti[t], 1.0f);
}

__global__ void __launch_bounds__(256) scan3_kernel() {
    int i = blockIdx.x * 256 + threadIdx.x;
    if (i >= NN) return;
    int s = g_start[i] + g_bsum[i >> 8];
    g_start[i] = s;
    g_cursor[i] = s;
    g_winv[i] = 1.0f / fmaxf((float)g_degi[i], 1.0f);
}

__global__ void __launch_bounds__(256) place_kernel(const void* __restrict__ ei) {
    int e = blockIdx.x * blockDim.x + threadIdx.x;
    if (e >= EE) return;
    unsigned s = (unsigned)ld_ei(ei, e);
    unsigned d = (unsigned)ld_ei(ei, (long long)EE + e);
    if (s >= NN || d >= NN) return;
    int pos = atomicAdd(&g_cursor[d], 1);
    g_csr[pos] = (int)s;
}

// ---------------- asymmetric bf16x2 GEMM, phase-resident B (no inner syncs) ----------------
// 256 threads, 8 warps (2x4 grid, warp tile 64x32), block tile 128x128.
// smem: A single plane [128][68] + B two planes [128][68] each = 102 KB -> 2 blocks/SM.
extern __shared__ unsigned sm_dyn[];
#define AS_STR 68
#define GEMM_SMEM (3 * 128 * AS_STR * 4)   // 104448 B

__device__ __forceinline__ void issue_b_full(const unsigned* __restrict__ WT,
                                             unsigned sa0, unsigned sa1, int tid) {
    // full phase B: 2 planes x 128 rows x 16 uint4 = 4096 uint4 slots
    #pragma unroll
    for (int i = 0; i < 16; i++) {
        int slot = tid + 256 * i;
        int pl = slot >> 11;
        int rem = slot & 2047;
        int n = rem >> 4;
        int u = rem & 15;
        const unsigned* src = WT + ((size_t)pl * 128 + n) * 64 + u * 4;
        unsigned dst = (pl ? sa1 : sa0) + (unsigned)(n * AS_STR + u * 4) * 4;
        asm volatile("cp.async.cg.shared.global [%0], [%1], 16;" :: "r"(dst), "l"(src));
    }
}

__global__ void __launch_bounds__(256, 2) gemm_bf16x2_kernel(const float* __restrict__ X,
                                                             int matL, int matR,
                                                             unsigned* __restrict__ Pout,
                                                             unsigned* __restrict__ Qout) {
    unsigned* As0 = sm_dyn;                       // [128][AS_STR]
    unsigned* Bs0 = sm_dyn + 128 * AS_STR;        // plane 0
    unsigned* Bs1 = sm_dyn + 2 * 128 * AS_STR;    // plane 1

    int tid = threadIdx.x;
    int warp = tid >> 5, lane = tid & 31;
    int g = lane >> 2, t = lane & 3;
    int wm = (warp >> 2) * 64;
    int wn = (warp & 3) * 32;
    int row0 = blockIdx.x * 128;

    unsigned bs0a = (unsigned)__cvta_generic_to_shared(Bs0);
    unsigned bs1a = (unsigned)__cvta_generic_to_shared(Bs1);

    const unsigned* WTs[2] = {&g_wspT[matL][0][0][0], &g_wspT[matR][0][0][0]};

    // issue full phase-0 B load; overlaps with A pack
    issue_b_full(WTs[0], bs0a, bs1a, tid);
    asm volatile("cp.async.commit_group;");

    // ---- A phase: pack fp32 -> single bf16 plane ----
    #pragma unroll
    for (int i = 0; i < 16; i++) {
        int slot = tid + 256 * i;
        int m = slot >> 5;
        int k4 = (slot & 31) * 4;
        int r = row0 + m;
        float4 av = (r < NN) ? *(const float4*)(X + (size_t)r * DD + k4)
                             : make_float4(0.f, 0.f, 0.f, 0.f);
        unsigned p0 = pack_bf2(av.x, av.y);
        unsigned q0 = pack_bf2(av.z, av.w);
        int k2 = k4 >> 1;
        *(uint2*)&As0[m * AS_STR + k2] = make_uint2(p0, q0);
    }

    asm volatile("cp.async.wait_group 0;" ::: "memory");
    __syncthreads();

    int arow = (lane & 7) + ((lane & 8) ? 8 : 0);
    int akb = (lane & 16) ? 16 : 0;
    int brow = (lane & 7) + ((lane & 16) ? 8 : 0);
    int bkb = (lane & 8) ? 16 : 0;

    unsigned a0base = (unsigned)__cvta_generic_to_shared(As0) + (wm + arow) * (AS_STR * 4) + akb;
    unsigned b0base = bs0a + (wn + brow) * (AS_STR * 4) + bkb;
    unsigned b1base = bs1a + (wn + brow) * (AS_STR * 4) + bkb;

    float acc[4][4][4];
    #pragma unroll
    for (int a = 0; a < 4; a++)
        #pragma unroll
        for (int b = 0; b < 4; b++)
            #pragma unroll
            for (int c = 0; c < 4; c++) acc[a][b][c] = 0.0f;

    #pragma unroll
    for (int phase = 0; phase < 2; phase++) {
        // 8 K-chunks, zero synchronization
        #pragma unroll
        for (int c = 0; c < 8; c++) {
            int ko2 = c * 8;
            unsigned a0f[4][4];
            #pragma unroll
            for (int mt = 0; mt < 4; mt++) {
                unsigned off = mt * 16 * (AS_STR * 4) + ko2 * 4;
                ldsm_x4(a0f[mt][0], a0f[mt][1], a0f[mt][2], a0f[mt][3], a0base + off);
            }
            #pragma unroll
            for (int ntp = 0; ntp < 2; ntp++) {
                unsigned off = ntp * 16 * (AS_STR * 4) + ko2 * 4;
                unsigned p0r0, p0r1, p0r2, p0r3, p1r0, p1r1, p1r2, p1r3;
                ldsm_x4(p0r0, p0r1, p0r2, p0r3, b0base + off);
                ldsm_x4(p1r0, p1r1, p1r2, p1r3, b1base + off);
                unsigned bh0[2] = {p0r0, p0r1}, bh1[2] = {p0r2, p0r3};
                unsigned bl0[2] = {p1r0, p1r1}, bl1[2] = {p1r2, p1r3};
                #pragma unroll
                for (int mt = 0; mt < 4; mt++) {
                    mma_bf16(acc[mt][2 * ntp], a0f[mt], bh0);
                    mma_bf16(acc[mt][2 * ntp], a0f[mt], bl0);
                    mma_bf16(acc[mt][2 * ntp + 1], a0f[mt], bh1);
                    mma_bf16(acc[mt][2 * ntp + 1], a0f[mt], bl1);
                }
            }
        }
        // epilogue for this phase
        unsigned* Out = phase ? Qout : Pout;
        #pragma unroll
        for (int mt = 0; mt < 4; mt++) {
            #pragma unroll
            for (int nt = 0; nt < 4; nt++) {
                int r = row0 + wm + mt * 16 + g;
                int cc = wn + nt * 8 + 2 * t;
                if (r < NN)
                    Out[(size_t)r * 64 + (cc >> 1)] = pack_bf2(acc[mt][nt][0], acc[mt][nt][1]);
                if (r + 8 < NN)
                    Out[(size_t)(r + 8) * 64 + (cc >> 1)] = pack_bf2(acc[mt][nt][2], acc[mt][nt][3]);
                acc[mt][nt][0] = acc[mt][nt][1] = acc[mt][nt][2] = acc[mt][nt][3] = 0.0f;
            }
        }
        if (phase == 0) {
            __syncthreads();   // all warps done reading phase-0 B
            issue_b_full(WTs[1], bs0a, bs1a, tid);
            asm volatile("cp.async.commit_group;");
            asm volatile("cp.async.wait_group 0;" ::: "memory");
            __syncthreads();
        }
    }
}

// ---------------- CSR gather (bf16 P + bf16 Q), warp per node ----------------
__global__ void __launch_bounds__(256) gather_kernel(const unsigned* __restrict__ P,
                                                     const unsigned* __restrict__ Q,
                                                     const float* __restrict__ bias,
                                                     float* __restrict__ H) {
    int node = blockIdx.x * 8 + (threadIdx.x >> 5);
    int lane = threadIdx.x & 31;
    int s = g_start[node];
    int d = g_degi[node];
    float4 acc = make_float4(0.f, 0.f, 0.f, 0.f);
    for (int j = 0; j < d; j++) {
        int src = g_csr[s + j];
        uint2 v = ((const uint2*)(P + (size_t)src * 64))[lane];
        acc_bf2(acc, v);
    }
    float w = g_winv[node];
    float4 q = make_float4(0.f, 0.f, 0.f, 0.f);
    acc_bf2(q, ((const uint2*)(Q + (size_t)node * 64))[lane]);
    float4 b = ((const float4*)bias)[lane];
    float4 o;
    o.x = fmaxf(acc.x * w + q.x + b.x, 0.0f);
    o.y = fmaxf(acc.y * w + q.y + b.y, 0.0f);
    o.z = fmaxf(acc.z * w + q.z + b.z, 0.0f);
    o.w = fmaxf(acc.w * w + q.w + b.w, 0.0f);
    ((float4*)(H + (size_t)node * DD))[lane] = o;
}

// ---------------- layer-2 gather fused with layer-3 projection -> z ----------------
__global__ void __launch_bounds__(256) gather2z_kernel(const unsigned* __restrict__ P,
                                                       const unsigned* __restrict__ Q,
                                                       const float* __restrict__ bias) {
    int node = blockIdx.x * 8 + (threadIdx.x >> 5);
    int lane = threadIdx.x & 31;
    int s = g_start[node];
    int d = g_degi[node];
    float4 acc = make_float4(0.f, 0.f, 0.f, 0.f);
    for (int j = 0; j < d; j++) {
        int src = g_csr[s + j];
        uint2 v = ((const uint2*)(P + (size_t)src * 64))[lane];
        acc_bf2(acc, v);
    }
    float w = g_winv[node];
    float4 q = make_float4(0.f, 0.f, 0.f, 0.f);
    acc_bf2(q, ((const uint2*)(Q + (size_t)node * 64))[lane]);
    float4 b = ((const float4*)bias)[lane];
    float hv[4];
    hv[0] = fmaxf(acc.x * w + q.x + b.x, 0.0f);
    hv[1] = fmaxf(acc.y * w + q.y + b.y, 0.0f);
    hv[2] = fmaxf(acc.z * w + q.z + b.z, 0.0f);
    hv[3] = fmaxf(acc.w * w + q.w + b.w, 0.0f);
    float s0 = 0.f, s1 = 0.f, s2 = 0.f, s3 = 0.f;
    #pragma unroll
    for (int j = 0; j < 4; j++) {
        int k = lane * 4 + j;
        s0 += hv[j] * g_Wcl[k * 2 + 0];
        s1 += hv[j] * g_Wcl[k * 2 + 1];
        s2 += hv[j] * g_Wcr[k * 2 + 0];
        s3 += hv[j] * g_Wcr[k * 2 + 1];
    }
    #pragma unroll
    for (int o = 16; o > 0; o >>= 1) {
        s0 += __shfl_down_sync(0xFFFFFFFFu, s0, o);
        s1 += __shfl_down_sync(0xFFFFFFFFu, s1, o);
        s2 += __shfl_down_sync(0xFFFFFFFFu, s2, o);
        s3 += __shfl_down_sync(0xFFFFFFFFu, s3, o);
    }
    if (lane == 0) ((float4*)g_z)[node] = make_float4(s0, s1, s2, s3);
}

// ---------------- layer-3 fold ----------------
__global__ void foldW_kernel(const float* __restrict__ Wl3, const float* __restrict__ Wr3,
                             const float* __restrict__ bl3, const float* __restrict__ Wlin,
                             const float* __restrict__ blin) {
    int k = threadIdx.x;
    float a0 = 0.f, a1 = 0.f, b0 = 0.f, b1 = 0.f;
    for (int m = 0; m < DD; m++) {
        float wl = Wl3[k * DD + m], wr = Wr3[k * DD + m];
        float l0 = Wlin[m * 2 + 0], l1 = Wlin[m * 2 + 1];
        a0 += wl * l0; a1 += wl * l1;
        b0 += wr * l0; b1 += wr * l1;
    }
    g_Wcl[k * 2 + 0] = a0; g_Wcl[k * 2 + 1] = a1;
    g_Wcr[k * 2 + 0] = b0; g_Wcr[k * 2 + 1] = b1;
    if (k < 2) {
        float cv = blin[k];
        for (int m = 0; m < DD; m++) cv += bl3[m] * Wlin[m * 2 + k];
        g_cb[k] = cv;
    }
}

// ---------------- layer-3 pooled reduction ----------------
__global__ void __launch_bounds__(256) pool3_kernel(const void* __restrict__ batch) {
    __shared__ float sh[NG * 2];
    for (int i = threadIdx.x; i < NG * 2; i += blockDim.x) sh[i] = 0.0f;
    __syncthreads();
    int n = blockIdx.x * 256 + threadIdx.x;
    if (n < NN) {
        int s = g_start[n], d = g_degi[n];
        float s0 = 0.f, s1 = 0.f;
        for (int j = 0; j < d; j++) {
            int src = g_csr[s + j];
            float2 zl = *(const float2*)(g_z + (size_t)src * 4);
            s0 += zl.x; s1 += zl.y;
        }
        float w = g_winv[n];
        unsigned gg = (unsigned)ld_b(batch, n);
        if (gg < NG) {
            float ci = g_cinv[gg];
            float2 zr = *(const float2*)(g_z + (size_t)n * 4 + 2);
            atomicAdd(&sh[gg * 2 + 0], ci * (w * s0 + zr.x));
            atomicAdd(&sh[gg * 2 + 1], ci * (w * s1 + zr.y));
        }
    }
    __syncthreads();
    for (int i = threadIdx.x; i < NG * 2; i += blockDim.x)
        if (sh[i] != 0.0f) atomicAdd(&g_acc[i], sh[i]);
}

__global__ void finalize_kernel(float* __restrict__ out) {
    int t = threadIdx.x;
    if (t < NG * 2) out[t] = g_acc[t] + g_cb[t & 1];
}

// ---------------- host launcher ----------------
extern "C" void kernel_launch(void* const* d_in, const int* in_sizes, int n_in,
                              void* d_out, int out_size) {
    const float* x = (const float*)d_in[0];
    const void* ei = d_in[1];
    const void* batch = d_in[2];
    const float* Wl1 = (const float*)d_in[3];
    const float* bl1 = (const float*)d_in[4];
    const float* Wr1 = (const float*)d_in[5];
    const float* Wl2 = (const float*)d_in[6];
    const float* bl2 = (const float*)d_in[7];
    const float* Wr2 = (const float*)d_in[8];
    const float* Wl3 = (const float*)d_in[9];
    const float* bl3 = (const float*)d_in[10];
    const float* Wr3 = (const float*)d_in[11];
    const float* Wlin = (const float*)d_in[12];
    const float* blin = (const float*)d_in[13];
    float* out = (float*)d_out;

    unsigned *pp = nullptr, *qp = nullptr;
    float* h1p = nullptr;
    cudaGetSymbolAddress((void**)&pp, g_pb);
    cudaGetSymbolAddress((void**)&qp, g_qb);
    cudaGetSymbolAddress((void**)&h1p, g_h1);

    cudaFuncSetAttribute(gemm_bf16x2_kernel,
                         cudaFuncAttributeMaxDynamicSharedMemorySize, GEMM_SMEM);

    const int nb = (NN + 255) / 256;           // 391
    const int gemm_blocks = (NN + 127) / 128;  // 782

    init_kernel<<<520, 256>>>(ei, batch, Wl1, Wr1, Wl2, Wr2);
    deg_cnt_kernel<<<(EE + 255) / 256, 256>>>(ei, batch);
    scan1_kernel<<<nb, 256>>>();
    gemm_bf16x2_kernel<<<gemm_blocks, 256, GEMM_SMEM>>>(x, 0, 1, pp, qp);   // profile slot 4
    scan2_kernel<<<1, 512>>>(nb);
    scan3_kernel<<<nb, 256>>>();
    place_kernel<<<(EE + 255) / 256, 256>>>(ei);
    gather_kernel<<<NN / 8, 256>>>(pp, qp, bl1, h1p);
    gemm_bf16x2_kernel<<<gemm_blocks, 256, GEMM_SMEM>>>(h1p, 2, 3, pp, qp);
    foldW_kernel<<<1, 128>>>(Wl3, Wr3, bl3, Wlin, blin);
    gather2z_kernel<<<NN / 8, 256>>>(pp, qp, bl2);
    pool3_kernel<<<nb, 256>>>(batch);
    finalize_kernel<<<1, 128>>>(out);
}

// round 15
// speedup vs baseline: 1.5041x; 1.0400x over previous
#include <cuda_runtime.h>
#include <cstdint>

#define NN 100000
#define EE 1600000
#define DD 128
#define NG 64

// ---------------- scratch (static device globals; no allocation) ----------------
__device__ int      g_ei64, g_b64;
__device__ int      g_degi[NN];
__device__ int      g_start[NN];
__device__ int      g_cursor[NN];
__device__ int      g_bsum[512];
__device__ int      g_cnti[NG];
__device__ int      g_csr[EE];
__device__ float    g_winv[NN];
__device__ float    g_cinv[NG];
__device__ unsigned g_pb[(size_t)NN * 64];    // P packed bf16x2
__device__ unsigned g_qb[(size_t)NN * 64];    // Q packed bf16x2
__device__ unsigned g_h1b[(size_t)NN * 64];   // h1 packed bf16x2
__device__ float    g_z[(size_t)NN * 4];
__device__ unsigned g_wspT[4][2][DD][64];     // pre-split W, transposed [mat][plane][n][k2]
__device__ float    g_Wcl[DD * 2];
__device__ float    g_Wcr[DD * 2];
__device__ float    g_cb[2];
__device__ float    g_acc[NG * 2];

// ---------------- helpers ----------------
__device__ __forceinline__ unsigned pack_bf2(float lo, float hi) {
    unsigned r;
    asm("cvt.rn.bf16x2.f32 %0, %1, %2;" : "=r"(r) : "f"(hi), "f"(lo));
    return r;
}
__device__ __forceinline__ void split2(float x0, float x1, unsigned& p0, unsigned& p1) {
    p0 = pack_bf2(x0, x1);
    float h0 = __uint_as_float(p0 << 16);
    float h1 = __uint_as_float(p0 & 0xFFFF0000u);
    p1 = pack_bf2(x0 - h0, x1 - h1);
}
__device__ __forceinline__ void mma_bf16(float* d, const unsigned* a, const unsigned* b) {
    asm volatile(
        "mma.sync.aligned.m16n8k16.row.col.f32.bf16.bf16.f32 "
        "{%0,%1,%2,%3}, {%4,%5,%6,%7}, {%8,%9}, {%0,%1,%2,%3};"
        : "+f"(d[0]), "+f"(d[1]), "+f"(d[2]), "+f"(d[3])
        : "r"(a[0]), "r"(a[1]), "r"(a[2]), "r"(a[3]), "r"(b[0]), "r"(b[1]));
}
__device__ __forceinline__ void ldsm_x4(unsigned& r0, unsigned& r1, unsigned& r2, unsigned& r3,
                                        unsigned saddr) {
    asm volatile("ldmatrix.sync.aligned.m8n8.x4.shared.b16 {%0,%1,%2,%3}, [%4];"
                 : "=r"(r0), "=r"(r1), "=r"(r2), "=r"(r3) : "r"(saddr));
}
__device__ __forceinline__ void acc_bf2(float4& acc, uint2 v) {
    acc.x += __uint_as_float(v.x << 16);
    acc.y += __uint_as_float(v.x & 0xFFFF0000u);
    acc.z += __uint_as_float(v.y << 16);
    acc.w += __uint_as_float(v.y & 0xFFFF0000u);
}

__device__ __forceinline__ int ld_ei(const void* p, long long i) {
    return g_ei64 ? (int)((const long long*)p)[i] : ((const int*)p)[i];
}
__device__ __forceinline__ int ld_b(const void* p, long long i) {
    return g_b64 ? (int)((const long long*)p)[i] : ((const int*)p)[i];
}

// ---------------- K0: zero + presplit + detect + foldW (role-split) ----------------
__global__ void __launch_bounds__(256) init_kernel(const void* ei, const void* batch,
                                                   const float* __restrict__ Wl1,
                                                   const float* __restrict__ Wr1,
                                                   const float* __restrict__ Wl2,
                                                   const float* __restrict__ Wr2,
                                                   const float* __restrict__ Wl3,
                                                   const float* __restrict__ Wr3,
                                                   const float* __restrict__ bl3,
                                                   const float* __restrict__ Wlin,
                                                   const float* __restrict__ blin) {
    int bid = blockIdx.x;
    if (bid < 391) {
        int i = bid * 256 + threadIdx.x;
        if (i < NN) g_degi[i] = 0;
        if (i < NG) g_cnti[i] = 0;
        if (i < NG * 2) g_acc[i] = 0.0f;
    } else if (bid < 519) {
        int idx = (bid - 391) * 256 + threadIdx.x;
        int mat = idx >> 13;
        int rem = idx & 8191;
        int k2 = rem >> 7;
        int n = rem & 127;
        const float* W = (mat == 0) ? Wl1 : (mat == 1) ? Wr1 : (mat == 2) ? Wl2 : Wr2;
        float w0 = W[(2 * k2) * DD + n];
        float w1 = W[(2 * k2 + 1) * DD + n];
        unsigned p0, p1;
        split2(w0, w1, p0, p1);
        g_wspT[mat][0][n][k2] = p0;
        g_wspT[mat][1][n][k2] = p1;
    } else if (bid == 519) {
        if (threadIdx.x == 0) {
            const long long* p = (const long long*)ei;
            bool e64 = true;
            #pragma unroll
            for (int i = 0; i < 16; i++) {
                long long v = p[(size_t)i * 99991];
                if (v < 0 || v >= NN) e64 = false;
            }
            g_ei64 = e64 ? 1 : 0;
            const long long* q = (const long long*)batch;
            bool b64 = true;
            #pragma unroll
            for (int i = 0; i < 8; i++) {
                long long v = q[NN / 2 - 1 - i * 37];
                if (v < 0 || v >= NG) b64 = false;
            }
            g_b64 = b64 ? 1 : 0;
        }
    } else {  // bid == 520: fold layer 3 through the linear head
        int k = threadIdx.x;
        if (k < DD) {
            float a0 = 0.f, a1 = 0.f, b0 = 0.f, b1 = 0.f;
            for (int m = 0; m < DD; m++) {
                float wl = Wl3[k * DD + m], wr = Wr3[k * DD + m];
                float l0 = Wlin[m * 2 + 0], l1 = Wlin[m * 2 + 1];
                a0 += wl * l0; a1 += wl * l1;
                b0 += wr * l0; b1 += wr * l1;
            }
            g_Wcl[k * 2 + 0] = a0; g_Wcl[k * 2 + 1] = a1;
            g_Wcr[k * 2 + 0] = b0; g_Wcr[k * 2 + 1] = b1;
            if (k < 2) {
                float cv = blin[k];
                for (int m = 0; m < DD; m++) cv += bl3[m] * Wlin[m * 2 + k];
                g_cb[k] = cv;
            }
        }
    }
}

// ---------------- fused degree + batch histogram ----------------
__global__ void __launch_bounds__(256) deg_cnt_kernel(const void* __restrict__ ei,
                                                      const void* __restrict__ batch) {
    __shared__ int sh[NG];
    if (threadIdx.x < NG) sh[threadIdx.x] = 0;
    __syncthreads();
    int e = blockIdx.x * 256 + threadIdx.x;
    if (e < EE) {
        unsigned d = (unsigned)ld_ei(ei, (long long)EE + e);
        if (d < NN) atomicAdd(&g_degi[d], 1);
    }
    if (e < NN) {
        unsigned g = (unsigned)ld_b(batch, e);
        if (g < NG) atomicAdd(&sh[g], 1);
    }
    __syncthreads();
    if (threadIdx.x < NG && sh[threadIdx.x] != 0) atomicAdd(&g_cnti[threadIdx.x], sh[threadIdx.x]);
}

// ---------------- scans / CSR placement ----------------
__global__ void __launch_bounds__(256) scan1_kernel() {
    __shared__ int sdata[256];
    int t = threadIdx.x;
    int i = blockIdx.x * 256 + t;
    int v = (i < NN) ? g_degi[i] : 0;
    sdata[t] = v;
    __syncthreads();
    #pragma unroll
    for (int off = 1; off < 256; off <<= 1) {
        int x = (t >= off) ? sdata[t - off] : 0;
        __syncthreads();
        sdata[t] += x;
        __syncthreads();
    }
    int incl = sdata[t];
    if (i < NN) g_start[i] = incl - v;
    if (t == 255) g_bsum[blockIdx.x] = incl;
}

__global__ void __launch_bounds__(512) scan2_kernel(int nb) {
    __shared__ int sdata[512];
    int t = threadIdx.x;
    int v = (t < nb) ? g_bsum[t] : 0;
    sdata[t] = v;
    __syncthreads();
    #pragma unroll
    for (int off = 1; off < 512; off <<= 1) {
        int x = (t >= off) ? sdata[t - off] : 0;
        __syncthreads();
        sdata[t] += x;
        __syncthreads();
    }
    if (t < nb) g_bsum[t] = sdata[t] - v;
    if (t < NG) g_cinv[t] = 1.0f / fmaxf((float)g_cnti[t], 1.0f);
}

__global__ void __launch_bounds__(256) scan3_kernel() {
    int i = blockIdx.x * 256 + threadIdx.x;
    if (i >= NN) return;
    int s = g_start[i] + g_bsum[i >> 8];
    g_start[i] = s;
    g_cursor[i] = s;
    g_winv[i] = 1.0f / fmaxf((float)g_degi[i], 1.0f);
}

__global__ void __launch_bounds__(256) place_kernel(const void* __restrict__ ei) {
    int e = blockIdx.x * blockDim.x + threadIdx.x;
    if (e >= EE) return;
    unsigned s = (unsigned)ld_ei(ei, e);
    unsigned d = (unsigned)ld_ei(ei, (long long)EE + e);
    if (s >= NN || d >= NN) return;
    int pos = atomicAdd(&g_cursor[d], 1);
    g_csr[pos] = (int)s;
}

// ---------------- asymmetric bf16x2 GEMM, phase-resident B ----------------
// 256 threads, 8 warps (2x4 grid, warp tile 64x32), block tile 128x128.
// APACKED=0: X is fp32 rows (pack to bf16). APACKED=1: X is packed bf16x2 (cp.async copy).
extern __shared__ unsigned sm_dyn[];
#define AS_STR 68
#define GEMM_SMEM (3 * 128 * AS_STR * 4)   // 104448 B -> 2 blocks/SM

__device__ __forceinline__ void issue_b_full(const unsigned* __restrict__ WT,
                                             unsigned sa0, unsigned sa1, int tid) {
    #pragma unroll
    for (int i = 0; i < 16; i++) {
        int slot = tid + 256 * i;          // 4096 uint4 slots (2 planes)
        int pl = slot >> 11;
        int rem = slot & 2047;
        int n = rem >> 4;
        int u = rem & 15;
        const unsigned* src = WT + ((size_t)pl * 128 + n) * 64 + u * 4;
        unsigned dst = (pl ? sa1 : sa0) + (unsigned)(n * AS_STR + u * 4) * 4;
        asm volatile("cp.async.cg.shared.global [%0], [%1], 16;" :: "r"(dst), "l"(src));
    }
}

template <int APACKED>
__global__ void __launch_bounds__(256, 2) gemm_bf16x2_kernel(const void* __restrict__ Xv,
                                                             int matL, int matR,
                                                             unsigned* __restrict__ Pout,
                                                             unsigned* __restrict__ Qout) {
    unsigned* As0 = sm_dyn;                       // [128][AS_STR]
    unsigned* Bs0 = sm_dyn + 128 * AS_STR;
    unsigned* Bs1 = sm_dyn + 2 * 128 * AS_STR;

    int tid = threadIdx.x;
    int warp = tid >> 5, lane = tid & 31;
    int g = lane >> 2, t = lane & 3;
    int wm = (warp >> 2) * 64;
    int wn = (warp & 3) * 32;
    int row0 = blockIdx.x * 128;

    unsigned as0a = (unsigned)__cvta_generic_to_shared(As0);
    unsigned bs0a = (unsigned)__cvta_generic_to_shared(Bs0);
    unsigned bs1a = (unsigned)__cvta_generic_to_shared(Bs1);

    const unsigned* WTs[2] = {&g_wspT[matL][0][0][0], &g_wspT[matR][0][0][0]};

    issue_b_full(WTs[0], bs0a, bs1a, tid);

    if (APACKED) {
        // A already bf16x2 packed: straight cp.async copy (row = 16 uint4)
        const unsigned* X = (const unsigned*)Xv;
        #pragma unroll
        for (int i = 0; i < 8; i++) {
            int slot = tid + 256 * i;       // 2048 uint4 slots
            int m = slot >> 4;
            int u = slot & 15;
            int r = row0 + m;
            if (r < NN) {
                const unsigned* src = X + (size_t)r * 64 + u * 4;
                unsigned dst = as0a + (unsigned)(m * AS_STR + u * 4) * 4;
                asm volatile("cp.async.cg.shared.global [%0], [%1], 16;" :: "r"(dst), "l"(src));
            } else {
                *(uint4*)&As0[m * AS_STR + u * 4] = make_uint4(0, 0, 0, 0);
            }
        }
        asm volatile("cp.async.commit_group;");
    } else {
        asm volatile("cp.async.commit_group;");
        const float* X = (const float*)Xv;
        #pragma unroll
        for (int i = 0; i < 16; i++) {
            int slot = tid + 256 * i;
            int m = slot >> 5;
            int k4 = (slot & 31) * 4;
            int r = row0 + m;
            float4 av = (r < NN) ? *(const float4*)(X + (size_t)r * DD + k4)
                                 : make_float4(0.f, 0.f, 0.f, 0.f);
            unsigned p0 = pack_bf2(av.x, av.y);
            unsigned q0 = pack_bf2(av.z, av.w);
            int k2 = k4 >> 1;
            *(uint2*)&As0[m * AS_STR + k2] = make_uint2(p0, q0);
        }
    }

    asm volatile("cp.async.wait_group 0;" ::: "memory");
    __syncthreads();

    int arow = (lane & 7) + ((lane & 8) ? 8 : 0);
    int akb = (lane & 16) ? 16 : 0;
    int brow = (lane & 7) + ((lane & 16) ? 8 : 0);
    int bkb = (lane & 8) ? 16 : 0;

    unsigned a0base = as0a + (wm + arow) * (AS_STR * 4) + akb;
    unsigned b0base = bs0a + (wn + brow) * (AS_STR * 4) + bkb;
    unsigned b1base = bs1a + (wn + brow) * (AS_STR * 4) + bkb;

    float acc[4][4][4];
    #pragma unroll
    for (int a = 0; a < 4; a++)
        #pragma unroll
        for (int b = 0; b < 4; b++)
            #pragma unroll
            for (int c = 0; c < 4; c++) acc[a][b][c] = 0.0f;

    #pragma unroll
    for (int phase = 0; phase < 2; phase++) {
        #pragma unroll
        for (int c = 0; c < 8; c++) {
            int ko2 = c * 8;
            unsigned a0f[4][4];
            #pragma unroll
            for (int mt = 0; mt < 4; mt++) {
                unsigned off = mt * 16 * (AS_STR * 4) + ko2 * 4;
                ldsm_x4(a0f[mt][0], a0f[mt][1], a0f[mt][2], a0f[mt][3], a0base + off);
            }
            #pragma unroll
            for (int ntp = 0; ntp < 2; ntp++) {
                unsigned off = ntp * 16 * (AS_STR * 4) + ko2 * 4;
                unsigned p0r0, p0r1, p0r2, p0r3, p1r0, p1r1, p1r2, p1r3;
                ldsm_x4(p0r0, p0r1, p0r2, p0r3, b0base + off);
                ldsm_x4(p1r0, p1r1, p1r2, p1r3, b1base + off);
                unsigned bh0[2] = {p0r0, p0r1}, bh1[2] = {p0r2, p0r3};
                unsigned bl0[2] = {p1r0, p1r1}, bl1[2] = {p1r2, p1r3};
                #pragma unroll
                for (int mt = 0; mt < 4; mt++) {
                    mma_bf16(acc[mt][2 * ntp], a0f[mt], bh0);
                    mma_bf16(acc[mt][2 * ntp], a0f[mt], bl0);
                    mma_bf16(acc[mt][2 * ntp + 1], a0f[mt], bh1);
                    mma_bf16(acc[mt][2 * ntp + 1], a0f[mt], bl1);
                }
            }
        }
        unsigned* Out = phase ? Qout : Pout;
        #pragma unroll
        for (int mt = 0; mt < 4; mt++) {
            #pragma unroll
            for (int nt = 0; nt < 4; nt++) {
                int r = row0 + wm + mt * 16 + g;
                int cc = wn + nt * 8 + 2 * t;
                if (r < NN)
                    Out[(size_t)r * 64 + (cc >> 1)] = pack_bf2(acc[mt][nt][0], acc[mt][nt][1]);
                if (r + 8 < NN)
                    Out[(size_t)(r + 8) * 64 + (cc >> 1)] = pack_bf2(acc[mt][nt][2], acc[mt][nt][3]);
                acc[mt][nt][0] = acc[mt][nt][1] = acc[mt][nt][2] = acc[mt][nt][3] = 0.0f;
            }
        }
        if (phase == 0) {
            __syncthreads();
            issue_b_full(WTs[1], bs0a, bs1a, tid);
            asm volatile("cp.async.commit_group;");
            asm volatile("cp.async.wait_group 0;" ::: "memory");
            __syncthreads();
        }
    }
}

// ---------------- CSR gather (bf16 P + bf16 Q) -> packed bf16 H ----------------
__global__ void __launch_bounds__(256) gather_kernel(const unsigned* __restrict__ P,
                                                     const unsigned* __restrict__ Q,
                                                     const float* __restrict__ bias,
                                                     unsigned* __restrict__ Hb) {
    int node = blockIdx.x * 8 + (threadIdx.x >> 5);
    int lane = threadIdx.x & 31;
    int s = g_start[node];
    int d = g_degi[node];
    float4 acc = make_float4(0.f, 0.f, 0.f, 0.f);
    int j = 0;
    for (; j + 2 <= d; j += 2) {
        int s0 = g_csr[s + j], s1 = g_csr[s + j + 1];
        uint2 v0 = ((const uint2*)(P + (size_t)s0 * 64))[lane];
        uint2 v1 = ((const uint2*)(P + (size_t)s1 * 64))[lane];
        acc_bf2(acc, v0);
        acc_bf2(acc, v1);
    }
    if (j < d) {
        uint2 v = ((const uint2*)(P + (size_t)g_csr[s + j] * 64))[lane];
        acc_bf2(acc, v);
    }
    float w = g_winv[node];
    float4 q = make_float4(0.f, 0.f, 0.f, 0.f);
    acc_bf2(q, ((const uint2*)(Q + (size_t)node * 64))[lane]);
    float4 b = ((const float4*)bias)[lane];
    float4 o;
    o.x = fmaxf(acc.x * w + q.x + b.x, 0.0f);
    o.y = fmaxf(acc.y * w + q.y + b.y, 0.0f);
    o.z = fmaxf(acc.z * w + q.z + b.z, 0.0f);
    o.w = fmaxf(acc.w * w + q.w + b.w, 0.0f);
    uint2 pk = make_uint2(pack_bf2(o.x, o.y), pack_bf2(o.z, o.w));
    ((uint2*)(Hb + (size_t)node * 64))[lane] = pk;
}

// ---------------- layer-2 gather fused with layer-3 projection -> z ----------------
__global__ void __launch_bounds__(256) gather2z_kernel(const unsigned* __restrict__ P,
                                                       const unsigned* __restrict__ Q,
                                                       const float* __restrict__ bias) {
    int node = blockIdx.x * 8 + (threadIdx.x >> 5);
    int lane = threadIdx.x & 31;
    int s = g_start[node];
    int d = g_degi[node];
    float4 acc = make_float4(0.f, 0.f, 0.f, 0.f);
    int j = 0;
    for (; j + 2 <= d; j += 2) {
        int s0 = g_csr[s + j], s1 = g_csr[s + j + 1];
        uint2 v0 = ((const uint2*)(P + (size_t)s0 * 64))[lane];
        uint2 v1 = ((const uint2*)(P + (size_t)s1 * 64))[lane];
        acc_bf2(acc, v0);
        acc_bf2(acc, v1);
    }
    if (j < d) {
        uint2 v = ((const uint2*)(P + (size_t)g_csr[s + j] * 64))[lane];
        acc_bf2(acc, v);
    }
    float w = g_winv[node];
    float4 q = make_float4(0.f, 0.f, 0.f, 0.f);
    acc_bf2(q, ((const uint2*)(Q + (size_t)node * 64))[lane]);
    float4 b = ((const float4*)bias)[lane];
    float hv[4];
    hv[0] = fmaxf(acc.x * w + q.x + b.x, 0.0f);
    hv[1] = fmaxf(acc.y * w + q.y + b.y, 0.0f);
    hv[2] = fmaxf(acc.z * w + q.z + b.z, 0.0f);
    hv[3] = fmaxf(acc.w * w + q.w + b.w, 0.0f);
    float s0 = 0.f, s1 = 0.f, s2 = 0.f, s3 = 0.f;
    #pragma unroll
    for (int jj = 0; jj < 4; jj++) {
        int k = lane * 4 + jj;
        s0 += hv[jj] * g_Wcl[k * 2 + 0];
        s1 += hv[jj] * g_Wcl[k * 2 + 1];
        s2 += hv[jj] * g_Wcr[k * 2 + 0];
        s3 += hv[jj] * g_Wcr[k * 2 + 1];
    }
    #pragma unroll
    for (int o = 16; o > 0; o >>= 1) {
        s0 += __shfl_down_sync(0xFFFFFFFFu, s0, o);
        s1 += __shfl_down_sync(0xFFFFFFFFu, s1, o);
        s2 += __shfl_down_sync(0xFFFFFFFFu, s2, o);
        s3 += __shfl_down_sync(0xFFFFFFFFu, s3, o);
    }
    if (lane == 0) ((float4*)g_z)[node] = make_float4(s0, s1, s2, s3);
}

// ---------------- layer-3 pooled reduction ----------------
__global__ void __launch_bounds__(256) pool3_kernel(const void* __restrict__ batch) {
    __shared__ float sh[NG * 2];
    for (int i = threadIdx.x; i < NG * 2; i += blockDim.x) sh[i] = 0.0f;
    __syncthreads();
    int n = blockIdx.x * 256 + threadIdx.x;
    if (n < NN) {
        int s = g_start[n], d = g_degi[n];
        float s0 = 0.f, s1 = 0.f;
        for (int j = 0; j < d; j++) {
            int src = g_csr[s + j];
            float2 zl = *(const float2*)(g_z + (size_t)src * 4);
            s0 += zl.x; s1 += zl.y;
        }
        float w = g_winv[n];
        unsigned gg = (unsigned)ld_b(batch, n);
        if (gg < NG) {
            float ci = g_cinv[gg];
            float2 zr = *(const float2*)(g_z + (size_t)n * 4 + 2);
            atomicAdd(&sh[gg * 2 + 0], ci * (w * s0 + zr.x));
            atomicAdd(&sh[gg * 2 + 1], ci * (w * s1 + zr.y));
        }
    }
    __syncthreads();
    for (int i = threadIdx.x; i < NG * 2; i += blockDim.x)
        if (sh[i] != 0.0f) atomicAdd(&g_acc[i], sh[i]);
}

__global__ void finalize_kernel(float* __restrict__ out) {
    int t = threadIdx.x;
    if (t < NG * 2) out[t] = g_acc[t] + g_cb[t & 1];
}

// ---------------- host launcher ----------------
extern "C" void kernel_launch(void* const* d_in, const int* in_sizes, int n_in,
                              void* d_out, int out_size) {
    const float* x = (const float*)d_in[0];
    const void* ei = d_in[1];
    const void* batch = d_in[2];
    const float* Wl1 = (const float*)d_in[3];
    const float* bl1 = (const float*)d_in[4];
    const float* Wr1 = (const float*)d_in[5];
    const float* Wl2 = (const float*)d_in[6];
    const float* bl2 = (const float*)d_in[7];
    const float* Wr2 = (const float*)d_in[8];
    const float* Wl3 = (const float*)d_in[9];
    const float* bl3 = (const float*)d_in[10];
    const float* Wr3 = (const float*)d_in[11];
    const float* Wlin = (const float*)d_in[12];
    const float* blin = (const float*)d_in[13];
    float* out = (float*)d_out;

    unsigned *pp = nullptr, *qp = nullptr, *h1p = nullptr;
    cudaGetSymbolAddress((void**)&pp, g_pb);
    cudaGetSymbolAddress((void**)&qp, g_qb);
    cudaGetSymbolAddress((void**)&h1p, g_h1b);

    cudaFuncSetAttribute(gemm_bf16x2_kernel<0>,
                         cudaFuncAttributeMaxDynamicSharedMemorySize, GEMM_SMEM);
    cudaFuncSetAttribute(gemm_bf16x2_kernel<1>,
                         cudaFuncAttributeMaxDynamicSharedMemorySize, GEMM_SMEM);

    const int nb = (NN + 255) / 256;           // 391
    const int gemm_blocks = (NN + 127) / 128;  // 782

    init_kernel<<<521, 256>>>(ei, batch, Wl1, Wr1, Wl2, Wr2, Wl3, Wr3, bl3, Wlin, blin);
    deg_cnt_kernel<<<(EE + 255) / 256, 256>>>(ei, batch);
    scan1_kernel<<<nb, 256>>>();
    gemm_bf16x2_kernel<0><<<gemm_blocks, 256, GEMM_SMEM>>>(x, 0, 1, pp, qp);  // profile slot 4
    scan2_kernel<<<1, 512>>>(nb);
    scan3_kernel<<<nb, 256>>>();
    place_kernel<<<(EE + 255) / 256, 256>>>(ei);
    gather_kernel<<<NN / 8, 256>>>(pp, qp, bl1, h1p);
    gemm_bf16x2_kernel<1><<<gemm_blocks, 256, GEMM_SMEM>>>(h1p, 2, 3, pp, qp);
    gather2z_kernel<<<NN / 8, 256>>>(pp, qp, bl2);
    pool3_kernel<<<nb, 256>>>(batch);
    finalize_kernel<<<1, 128>>>(out);
}

// round 16
// speedup vs baseline: 1.5527x; 1.0323x over previous
#include <cuda_runtime.h>
#include <cstdint>

#define NN 100000
#define EE 1600000
#define DD 128
#define NG 64

// ---------------- scratch (static device globals; no allocation) ----------------
__device__ int      g_ei64, g_b64;
__device__ int      g_degi[NN];
__device__ int      g_start[NN];
__device__ int      g_cursor[NN];
__device__ int      g_bsum[512];
__device__ int      g_cnti[NG];
__device__ int      g_csr[EE];
__device__ float    g_winv[NN];
__device__ float    g_cinv[NG];
__device__ unsigned g_pb[(size_t)NN * 64];    // P packed bf16x2
__device__ unsigned g_qb[(size_t)NN * 64];    // Q packed bf16x2
__device__ unsigned g_h1b[(size_t)NN * 64];   // h1 packed bf16x2
__device__ float    g_z[(size_t)NN * 4];
__device__ unsigned g_wspT[4][2][DD][64];     // pre-split W, transposed [mat][plane][n][k2]
__device__ float    g_Wcl[DD * 2];
__device__ float    g_Wcr[DD * 2];
__device__ float    g_cb[2];
__device__ float    g_acc[NG * 2];

// ---------------- helpers ----------------
__device__ __forceinline__ unsigned pack_bf2(float lo, float hi) {
    unsigned r;
    asm("cvt.rn.bf16x2.f32 %0, %1, %2;" : "=r"(r) : "f"(hi), "f"(lo));
    return r;
}
__device__ __forceinline__ void split2(float x0, float x1, unsigned& p0, unsigned& p1) {
    p0 = pack_bf2(x0, x1);
    float h0 = __uint_as_float(p0 << 16);
    float h1 = __uint_as_float(p0 & 0xFFFF0000u);
    p1 = pack_bf2(x0 - h0, x1 - h1);
}
__device__ __forceinline__ void mma_bf16(float* d, const unsigned* a, const unsigned* b) {
    asm volatile(
        "mma.sync.aligned.m16n8k16.row.col.f32.bf16.bf16.f32 "
        "{%0,%1,%2,%3}, {%4,%5,%6,%7}, {%8,%9}, {%0,%1,%2,%3};"
        : "+f"(d[0]), "+f"(d[1]), "+f"(d[2]), "+f"(d[3])
        : "r"(a[0]), "r"(a[1]), "r"(a[2]), "r"(a[3]), "r"(b[0]), "r"(b[1]));
}
__device__ __forceinline__ void ldsm_x4(unsigned& r0, unsigned& r1, unsigned& r2, unsigned& r3,
                                        unsigned saddr) {
    asm volatile("ldmatrix.sync.aligned.m8n8.x4.shared.b16 {%0,%1,%2,%3}, [%4];"
                 : "=r"(r0), "=r"(r1), "=r"(r2), "=r"(r3) : "r"(saddr));
}
__device__ __forceinline__ void acc_bf2(float4& acc, uint2 v) {
    acc.x += __uint_as_float(v.x << 16);
    acc.y += __uint_as_float(v.x & 0xFFFF0000u);
    acc.z += __uint_as_float(v.y << 16);
    acc.w += __uint_as_float(v.y & 0xFFFF0000u);
}

__device__ __forceinline__ int ld_ei(const void* p, long long i) {
    return g_ei64 ? (int)((const long long*)p)[i] : ((const int*)p)[i];
}
__device__ __forceinline__ int ld_b(const void* p, long long i) {
    return g_b64 ? (int)((const long long*)p)[i] : ((const int*)p)[i];
}

// ---------------- K0: zero + presplit + detect + foldW (role-split) ----------------
__global__ void __launch_bounds__(256) init_kernel(const void* ei, const void* batch,
                                                   const float* __restrict__ Wl1,
                                                   const float* __restrict__ Wr1,
                                                   const float* __restrict__ Wl2,
                                                   const float* __restrict__ Wr2,
                                                   const float* __restrict__ Wl3,
                                                   const float* __restrict__ Wr3,
                                                   const float* __restrict__ bl3,
                                                   const float* __restrict__ Wlin,
                                                   const float* __restrict__ blin) {
    int bid = blockIdx.x;
    if (bid < 391) {
        int i = bid * 256 + threadIdx.x;
        if (i < NN) g_degi[i] = 0;
        if (i < NG) g_cnti[i] = 0;
        if (i < NG * 2) g_acc[i] = 0.0f;
    } else if (bid < 519) {
        int idx = (bid - 391) * 256 + threadIdx.x;
        int mat = idx >> 13;
        int rem = idx & 8191;
        int k2 = rem >> 7;
        int n = rem & 127;
        const float* W = (mat == 0) ? Wl1 : (mat == 1) ? Wr1 : (mat == 2) ? Wl2 : Wr2;
        float w0 = W[(2 * k2) * DD + n];
        float w1 = W[(2 * k2 + 1) * DD + n];
        unsigned p0, p1;
        split2(w0, w1, p0, p1);
        g_wspT[mat][0][n][k2] = p0;
        g_wspT[mat][1][n][k2] = p1;
    } else if (bid == 519) {
        if (threadIdx.x == 0) {
            const long long* p = (const long long*)ei;
            bool e64 = true;
            #pragma unroll
            for (int i = 0; i < 16; i++) {
                long long v = p[(size_t)i * 99991];
                if (v < 0 || v >= NN) e64 = false;
            }
            g_ei64 = e64 ? 1 : 0;
            const long long* q = (const long long*)batch;
            bool b64 = true;
            #pragma unroll
            for (int i = 0; i < 8; i++) {
                long long v = q[NN / 2 - 1 - i * 37];
                if (v < 0 || v >= NG) b64 = false;
            }
            g_b64 = b64 ? 1 : 0;
        }
    } else {  // bid == 520: fold layer 3 through the linear head
        int k = threadIdx.x;
        if (k < DD) {
            float a0 = 0.f, a1 = 0.f, b0 = 0.f, b1 = 0.f;
            for (int m = 0; m < DD; m++) {
                float wl = Wl3[k * DD + m], wr = Wr3[k * DD + m];
                float l0 = Wlin[m * 2 + 0], l1 = Wlin[m * 2 + 1];
                a0 += wl * l0; a1 += wl * l1;
                b0 += wr * l0; b1 += wr * l1;
            }
            g_Wcl[k * 2 + 0] = a0; g_Wcl[k * 2 + 1] = a1;
            g_Wcr[k * 2 + 0] = b0; g_Wcr[k * 2 + 1] = b1;
            if (k < 2) {
                float cv = blin[k];
                for (int m = 0; m < DD; m++) cv += bl3[m] * Wlin[m * 2 + k];
                g_cb[k] = cv;
            }
        }
    }
}

// ---------------- fused degree + batch histogram ----------------
__global__ void __launch_bounds__(256) deg_cnt_kernel(const void* __restrict__ ei,
                                                      const void* __restrict__ batch) {
    __shared__ int sh[NG];
    if (threadIdx.x < NG) sh[threadIdx.x] = 0;
    __syncthreads();
    int e = blockIdx.x * 256 + threadIdx.x;
    if (e < EE) {
        unsigned d = (unsigned)ld_ei(ei, (long long)EE + e);
        if (d < NN) atomicAdd(&g_degi[d], 1);
    }
    if (e < NN) {
        unsigned g = (unsigned)ld_b(batch, e);
        if (g < NG) atomicAdd(&sh[g], 1);
    }
    __syncthreads();
    if (threadIdx.x < NG && sh[threadIdx.x] != 0) atomicAdd(&g_cnti[threadIdx.x], sh[threadIdx.x]);
}

// ---------------- scans / CSR placement ----------------
__global__ void __launch_bounds__(256) scan1_kernel() {
    __shared__ int sdata[256];
    int t = threadIdx.x;
    int i = blockIdx.x * 256 + t;
    int v = (i < NN) ? g_degi[i] : 0;
    sdata[t] = v;
    __syncthreads();
    #pragma unroll
    for (int off = 1; off < 256; off <<= 1) {
        int x = (t >= off) ? sdata[t - off] : 0;
        __syncthreads();
        sdata[t] += x;
        __syncthreads();
    }
    int incl = sdata[t];
    if (i < NN) g_start[i] = incl - v;
    if (t == 255) g_bsum[blockIdx.x] = incl;
}

__global__ void __launch_bounds__(512) scan2_kernel(int nb) {
    __shared__ int sdata[512];
    int t = threadIdx.x;
    int v = (t < nb) ? g_bsum[t] : 0;
    sdata[t] = v;
    __syncthreads();
    #pragma unroll
    for (int off = 1; off < 512; off <<= 1) {
        int x = (t >= off) ? sdata[t - off] : 0;
        __syncthreads();
        sdata[t] += x;
        __syncthreads();
    }
    if (t < nb) g_bsum[t] = sdata[t] - v;
    if (t < NG) g_cinv[t] = 1.0f / fmaxf((float)g_cnti[t], 1.0f);
}

__global__ void __launch_bounds__(256) scan3_kernel() {
    int i = blockIdx.x * 256 + threadIdx.x;
    if (i >= NN) return;
    int s = g_start[i] + g_bsum[i >> 8];
    g_start[i] = s;
    g_cursor[i] = s;
    g_winv[i] = 1.0f / fmaxf((float)g_degi[i], 1.0f);
}

__global__ void __launch_bounds__(256) place_kernel(const void* __restrict__ ei) {
    int e = blockIdx.x * blockDim.x + threadIdx.x;
    if (e >= EE) return;
    unsigned s = (unsigned)ld_ei(ei, e);
    unsigned d = (unsigned)ld_ei(ei, (long long)EE + e);
    if (s >= NN || d >= NN) return;
    int pos = atomicAdd(&g_cursor[d], 1);
    g_csr[pos] = (int)s;
}

// ---------------- asymmetric bf16x2 GEMM, phase-resident B ----------------
extern __shared__ unsigned sm_dyn[];
#define AS_STR 68
#define GEMM_SMEM (3 * 128 * AS_STR * 4)   // 104448 B -> 2 blocks/SM

__device__ __forceinline__ void issue_b_full(const unsigned* __restrict__ WT,
                                             unsigned sa0, unsigned sa1, int tid) {
    #pragma unroll
    for (int i = 0; i < 16; i++) {
        int slot = tid + 256 * i;          // 4096 uint4 slots (2 planes)
        int pl = slot >> 11;
        int rem = slot & 2047;
        int n = rem >> 4;
        int u = rem & 15;
        const unsigned* src = WT + ((size_t)pl * 128 + n) * 64 + u * 4;
        unsigned dst = (pl ? sa1 : sa0) + (unsigned)(n * AS_STR + u * 4) * 4;
        asm volatile("cp.async.cg.shared.global [%0], [%1], 16;" :: "r"(dst), "l"(src));
    }
}

template <int APACKED>
__global__ void __launch_bounds__(256, 2) gemm_bf16x2_kernel(const void* __restrict__ Xv,
                                                             int matL, int matR,
                                                             unsigned* __restrict__ Pout,
                                                             unsigned* __restrict__ Qout) {
    unsigned* As0 = sm_dyn;
    unsigned* Bs0 = sm_dyn + 128 * AS_STR;
    unsigned* Bs1 = sm_dyn + 2 * 128 * AS_STR;

    int tid = threadIdx.x;
    int warp = tid >> 5, lane = tid & 31;
    int g = lane >> 2, t = lane & 3;
    int wm = (warp >> 2) * 64;
    int wn = (warp & 3) * 32;
    int row0 = blockIdx.x * 128;

    unsigned as0a = (unsigned)__cvta_generic_to_shared(As0);
    unsigned bs0a = (unsigned)__cvta_generic_to_shared(Bs0);
    unsigned bs1a = (unsigned)__cvta_generic_to_shared(Bs1);

    const unsigned* WTs[2] = {&g_wspT[matL][0][0][0], &g_wspT[matR][0][0][0]};

    issue_b_full(WTs[0], bs0a, bs1a, tid);

    if (APACKED) {
        const unsigned* X = (const unsigned*)Xv;
        #pragma unroll
        for (int i = 0; i < 8; i++) {
            int slot = tid + 256 * i;
            int m = slot >> 4;
            int u = slot & 15;
            int r = row0 + m;
            if (r < NN) {
                const unsigned* src = X + (size_t)r * 64 + u * 4;
                unsigned dst = as0a + (unsigned)(m * AS_STR + u * 4) * 4;
                asm volatile("cp.async.cg.shared.global [%0], [%1], 16;" :: "r"(dst), "l"(src));
            } else {
                *(uint4*)&As0[m * AS_STR + u * 4] = make_uint4(0, 0, 0, 0);
            }
        }
        asm volatile("cp.async.commit_group;");
    } else {
        asm volatile("cp.async.commit_group;");
        const float* X = (const float*)Xv;
        #pragma unroll
        for (int i = 0; i < 16; i++) {
            int slot = tid + 256 * i;
            int m = slot >> 5;
            int k4 = (slot & 31) * 4;
            int r = row0 + m;
            float4 av = (r < NN) ? *(const float4*)(X + (size_t)r * DD + k4)
                                 : make_float4(0.f, 0.f, 0.f, 0.f);
            unsigned p0 = pack_bf2(av.x, av.y);
            unsigned q0 = pack_bf2(av.z, av.w);
            int k2 = k4 >> 1;
            *(uint2*)&As0[m * AS_STR + k2] = make_uint2(p0, q0);
        }
    }

    asm volatile("cp.async.wait_group 0;" ::: "memory");
    __syncthreads();

    int arow = (lane & 7) + ((lane & 8) ? 8 : 0);
    int akb = (lane & 16) ? 16 : 0;
    int brow = (lane & 7) + ((lane & 16) ? 8 : 0);
    int bkb = (lane & 8) ? 16 : 0;

    unsigned a0base = as0a + (wm + arow) * (AS_STR * 4) + akb;
    unsigned b0base = bs0a + (wn + brow) * (AS_STR * 4) + bkb;
    unsigned b1base = bs1a + (wn + brow) * (AS_STR * 4) + bkb;

    float acc[4][4][4];
    #pragma unroll
    for (int a = 0; a < 4; a++)
        #pragma unroll
        for (int b = 0; b < 4; b++)
            #pragma unroll
            for (int c = 0; c < 4; c++) acc[a][b][c] = 0.0f;

    #pragma unroll
    for (int phase = 0; phase < 2; phase++) {
        #pragma unroll
        for (int c = 0; c < 8; c++) {
            int ko2 = c * 8;
            unsigned a0f[4][4];
            #pragma unroll
            for (int mt = 0; mt < 4; mt++) {
                unsigned off = mt * 16 * (AS_STR * 4) + ko2 * 4;
                ldsm_x4(a0f[mt][0], a0f[mt][1], a0f[mt][2], a0f[mt][3], a0base + off);
            }
            #pragma unroll
            for (int ntp = 0; ntp < 2; ntp++) {
                unsigned off = ntp * 16 * (AS_STR * 4) + ko2 * 4;
                unsigned p0r0, p0r1, p0r2, p0r3, p1r0, p1r1, p1r2, p1r3;
                ldsm_x4(p0r0, p0r1, p0r2, p0r3, b0base + off);
                ldsm_x4(p1r0, p1r1, p1r2, p1r3, b1base + off);
                unsigned bh0[2] = {p0r0, p0r1}, bh1[2] = {p0r2, p0r3};
                unsigned bl0[2] = {p1r0, p1r1}, bl1[2] = {p1r2, p1r3};
                #pragma unroll
                for (int mt = 0; mt < 4; mt++) {
                    mma_bf16(acc[mt][2 * ntp], a0f[mt], bh0);
                    mma_bf16(acc[mt][2 * ntp], a0f[mt], bl0);
                    mma_bf16(acc[mt][2 * ntp + 1], a0f[mt], bh1);
                    mma_bf16(acc[mt][2 * ntp + 1], a0f[mt], bl1);
                }
            }
        }
        unsigned* Out = phase ? Qout : Pout;
        #pragma unroll
        for (int mt = 0; mt < 4; mt++) {
            #pragma unroll
            for (int nt = 0; nt < 4; nt++) {
                int r = row0 + wm + mt * 16 + g;
                int cc = wn + nt * 8 + 2 * t;
                if (r < NN)
                    Out[(size_t)r * 64 + (cc >> 1)] = pack_bf2(acc[mt][nt][0], acc[mt][nt][1]);
                if (r + 8 < NN)
                    Out[(size_t)(r + 8) * 64 + (cc >> 1)] = pack_bf2(acc[mt][nt][2], acc[mt][nt][3]);
                acc[mt][nt][0] = acc[mt][nt][1] = acc[mt][nt][2] = acc[mt][nt][3] = 0.0f;
            }
        }
        if (phase == 0) {
            __syncthreads();
            issue_b_full(WTs[1], bs0a, bs1a, tid);
            asm volatile("cp.async.commit_group;");
            asm volatile("cp.async.wait_group 0;" ::: "memory");
            __syncthreads();
        }
    }
}

// ---------------- CSR gather (bf16 P + bf16 Q) -> packed bf16 H ----------------
__global__ void __launch_bounds__(256) gather_kernel(const unsigned* __restrict__ P,
                                                     const unsigned* __restrict__ Q,
                                                     const float* __restrict__ bias,
                                                     unsigned* __restrict__ Hb) {
    int node = blockIdx.x * 8 + (threadIdx.x >> 5);
    int lane = threadIdx.x & 31;
    int s = g_start[node];
    int d = g_degi[node];
    float4 acc = make_float4(0.f, 0.f, 0.f, 0.f);
    int j = 0;
    for (; j + 2 <= d; j += 2) {
        int s0 = g_csr[s + j], s1 = g_csr[s + j + 1];
        uint2 v0 = ((const uint2*)(P + (size_t)s0 * 64))[lane];
        uint2 v1 = ((const uint2*)(P + (size_t)s1 * 64))[lane];
        acc_bf2(acc, v0);
        acc_bf2(acc, v1);
    }
    if (j < d) {
        uint2 v = ((const uint2*)(P + (size_t)g_csr[s + j] * 64))[lane];
        acc_bf2(acc, v);
    }
    float w = g_winv[node];
    float4 q = make_float4(0.f, 0.f, 0.f, 0.f);
    acc_bf2(q, ((const uint2*)(Q + (size_t)node * 64))[lane]);
    float4 b = ((const float4*)bias)[lane];
    float4 o;
    o.x = fmaxf(acc.x * w + q.x + b.x, 0.0f);
    o.y = fmaxf(acc.y * w + q.y + b.y, 0.0f);
    o.z = fmaxf(acc.z * w + q.z + b.z, 0.0f);
    o.w = fmaxf(acc.w * w + q.w + b.w, 0.0f);
    uint2 pk = make_uint2(pack_bf2(o.x, o.y), pack_bf2(o.z, o.w));
    ((uint2*)(Hb + (size_t)node * 64))[lane] = pk;
}

// ---------------- layer-2 gather fused with layer-3 projection -> z ----------------
__global__ void __launch_bounds__(256) gather2z_kernel(const unsigned* __restrict__ P,
                                                       const unsigned* __restrict__ Q,
                                                       const float* __restrict__ bias) {
    int node = blockIdx.x * 8 + (threadIdx.x >> 5);
    int lane = threadIdx.x & 31;
    int s = g_start[node];
    int d = g_degi[node];
    float4 acc = make_float4(0.f, 0.f, 0.f, 0.f);
    int j = 0;
    for (; j + 2 <= d; j += 2) {
        int s0 = g_csr[s + j], s1 = g_csr[s + j + 1];
        uint2 v0 = ((const uint2*)(P + (size_t)s0 * 64))[lane];
        uint2 v1 = ((const uint2*)(P + (size_t)s1 * 64))[lane];
        acc_bf2(acc, v0);
        acc_bf2(acc, v1);
    }
    if (j < d) {
        uint2 v = ((const uint2*)(P + (size_t)g_csr[s + j] * 64))[lane];
        acc_bf2(acc, v);
    }
    float w = g_winv[node];
    float4 q = make_float4(0.f, 0.f, 0.f, 0.f);
    acc_bf2(q, ((const uint2*)(Q + (size_t)node * 64))[lane]);
    float4 b = ((const float4*)bias)[lane];
    float hv[4];
    hv[0] = fmaxf(acc.x * w + q.x + b.x, 0.0f);
    hv[1] = fmaxf(acc.y * w + q.y + b.y, 0.0f);
    hv[2] = fmaxf(acc.z * w + q.z + b.z, 0.0f);
    hv[3] = fmaxf(acc.w * w + q.w + b.w, 0.0f);
    float s0 = 0.f, s1 = 0.f, s2 = 0.f, s3 = 0.f;
    #pragma unroll
    for (int jj = 0; jj < 4; jj++) {
        int k = lane * 4 + jj;
        s0 += hv[jj] * g_Wcl[k * 2 + 0];
        s1 += hv[jj] * g_Wcl[k * 2 + 1];
        s2 += hv[jj] * g_Wcr[k * 2 + 0];
        s3 += hv[jj] * g_Wcr[k * 2 + 1];
    }
    #pragma unroll
    for (int o = 16; o > 0; o >>= 1) {
        s0 += __shfl_down_sync(0xFFFFFFFFu, s0, o);
        s1 += __shfl_down_sync(0xFFFFFFFFu, s1, o);
        s2 += __shfl_down_sync(0xFFFFFFFFu, s2, o);
        s3 += __shfl_down_sync(0xFFFFFFFFu, s3, o);
    }
    if (lane == 0) ((float4*)g_z)[node] = make_float4(s0, s1, s2, s3);
}

// ---------------- layer-3 pooled reduction ----------------
__global__ void __launch_bounds__(256) pool3_kernel(const void* __restrict__ batch) {
    __shared__ float sh[NG * 2];
    for (int i = threadIdx.x; i < NG * 2; i += blockDim.x) sh[i] = 0.0f;
    __syncthreads();
    int n = blockIdx.x * 256 + threadIdx.x;
    if (n < NN) {
        int s = g_start[n], d = g_degi[n];
        float s0 = 0.f, s1 = 0.f;
        for (int j = 0; j < d; j++) {
            int src = g_csr[s + j];
            float2 zl = *(const float2*)(g_z + (size_t)src * 4);
            s0 += zl.x; s1 += zl.y;
        }
        float w = g_winv[n];
        unsigned gg = (unsigned)ld_b(batch, n);
        if (gg < NG) {
            float ci = g_cinv[gg];
            float2 zr = *(const float2*)(g_z + (size_t)n * 4 + 2);
            atomicAdd(&sh[gg * 2 + 0], ci * (w * s0 + zr.x));
            atomicAdd(&sh[gg * 2 + 1], ci * (w * s1 + zr.y));
        }
    }
    __syncthreads();
    for (int i = threadIdx.x; i < NG * 2; i += blockDim.x)
        if (sh[i] != 0.0f) atomicAdd(&g_acc[i], sh[i]);
}

__global__ void finalize_kernel(float* __restrict__ out) {
    int t = threadIdx.x;
    if (t < NG * 2) out[t] = g_acc[t] + g_cb[t & 1];
}

// ---------------- host launcher ----------------
extern "C" void kernel_launch(void* const* d_in, const int* in_sizes, int n_in,
                              void* d_out, int out_size) {
    const float* x = (const float*)d_in[0];
    const void* ei = d_in[1];
    const void* batch = d_in[2];
    const float* Wl1 = (const float*)d_in[3];
    const float* bl1 = (const float*)d_in[4];
    const float* Wr1 = (const float*)d_in[5];
    const float* Wl2 = (const float*)d_in[6];
    const float* bl2 = (const float*)d_in[7];
    const float* Wr2 = (const float*)d_in[8];
    const float* Wl3 = (const float*)d_in[9];
    const float* bl3 = (const float*)d_in[10];
    const float* Wr3 = (const float*)d_in[11];
    const float* Wlin = (const float*)d_in[12];
    const float* blin = (const float*)d_in[13];
    float* out = (float*)d_out;

    unsigned *pp = nullptr, *qp = nullptr, *h1p = nullptr;
    cudaGetSymbolAddress((void**)&pp, g_pb);
    cudaGetSymbolAddress((void**)&qp, g_qb);
    cudaGetSymbolAddress((void**)&h1p, g_h1b);

    cudaFuncSetAttribute(gemm_bf16x2_kernel<0>,
                         cudaFuncAttributeMaxDynamicSharedMemorySize, GEMM_SMEM);
    cudaFuncSetAttribute(gemm_bf16x2_kernel<1>,
                         cudaFuncAttributeMaxDynamicSharedMemorySize, GEMM_SMEM);

    const int nb = (NN + 255) / 256;           // 391
    const int gemm_blocks = (NN + 127) / 128;  // 782

    // Fork/join: gemm1 depends only on init (presplit); CSR build is independent.
    // Streams/events created per call — kernel_launch runs only a handful of times
    // (correctness + capture); no device memory is allocated.
    cudaStream_t s1;
    cudaStreamCreateWithFlags(&s1, cudaStreamNonBlocking);
    cudaEvent_t e0, e1;
    cudaEventCreateWithFlags(&e0, cudaEventDisableTiming);
    cudaEventCreateWithFlags(&e1, cudaEventDisableTiming);

    init_kernel<<<521, 256>>>(ei, batch, Wl1, Wr1, Wl2, Wr2, Wl3, Wr3, bl3, Wlin, blin);
    cudaEventRecord(e0, 0);

    // side stream: layer-1 GEMM
    cudaStreamWaitEvent(s1, e0, 0);
    gemm_bf16x2_kernel<0><<<gemm_blocks, 256, GEMM_SMEM, s1>>>(x, 0, 1, pp, qp);
    cudaEventRecord(e1, s1);

    // main stream: CSR build (concurrent with gemm1)
    deg_cnt_kernel<<<(EE + 255) / 256, 256>>>(ei, batch);
    scan1_kernel<<<nb, 256>>>();
    scan2_kernel<<<1, 512>>>(nb);
    scan3_kernel<<<nb, 256>>>();
    place_kernel<<<(EE + 255) / 256, 256>>>(ei);

    // join: gather1 needs both CSR and gemm1 outputs
    cudaStreamWaitEvent(0, e1, 0);
    gather_kernel<<<NN / 8, 256>>>(pp, qp, bl1, h1p);
    gemm_bf16x2_kernel<1><<<gemm_blocks, 256, GEMM_SMEM>>>(h1p, 2, 3, pp, qp);
    gather2z_kernel<<<NN / 8, 256>>>(pp, qp, bl2);
    pool3_kernel<<<nb, 256>>>(batch);
    finalize_kernel<<<1, 128>>>(out);
}